// round 11
// baseline (speedup 1.0000x reference)
#include <cuda_runtime.h>
#include <cuda_bf16.h>
#include <cstdint>
#include <cstddef>

// Problem constants
#define B_  4
#define T_  2048
#define C_  1024
#define H_  16
#define D_  64
#define M_TOK (B_ * T_)      // 8192
#define C3 (3 * C_)          // 3072
#define GK 1024              // K of both GEMMs

// ---------------------------------------------------------------------------
// Scratch (device globals; allocation in kernel_launch is forbidden)
// ---------------------------------------------------------------------------
__device__ __nv_bfloat16 g_qkvh[(size_t)M_TOK * C3]; // qkv hi (from GEMM epi)
__device__ __nv_bfloat16 g_qkvl[(size_t)M_TOK * C3]; // qkv lo
__device__ __nv_bfloat16 g_xhi[(size_t)M_TOK * C_];
__device__ __nv_bfloat16 g_xlo[(size_t)M_TOK * C_];
__device__ __nv_bfloat16 g_yhi[(size_t)M_TOK * C_];
__device__ __nv_bfloat16 g_ylo[(size_t)M_TOK * C_];
__device__ __nv_bfloat16 g_wahi[(size_t)C3 * C_];  // W_attn^T [3C][C]
__device__ __nv_bfloat16 g_walo[(size_t)C3 * C_];
__device__ __nv_bfloat16 g_wphi[(size_t)C_ * C_];  // W_proj^T [C][C]
__device__ __nv_bfloat16 g_wplo[(size_t)C_ * C_];

// ---------------------------------------------------------------------------
// PTX helpers
// ---------------------------------------------------------------------------
__device__ __forceinline__ uint32_t smem_u32(const void* p) {
    uint32_t a;
    asm("{ .reg .u64 t; cvta.to.shared.u64 t, %1; cvt.u32.u64 %0, t; }"
        : "=r"(a) : "l"(p));
    return a;
}
__device__ __forceinline__ void cp_async16(uint32_t dst, const void* src) {
    asm volatile("cp.async.cg.shared.global [%0], [%1], 16;"
                 :: "r"(dst), "l"(src) : "memory");
}
__device__ __forceinline__ void cp_commit() {
    asm volatile("cp.async.commit_group;" ::: "memory");
}
template <int N>
__device__ __forceinline__ void cp_wait() {
    asm volatile("cp.async.wait_group %0;" :: "n"(N) : "memory");
}
__device__ __forceinline__ void ldm_x4(uint32_t* r, uint32_t addr) {
    asm volatile("ldmatrix.sync.aligned.m8n8.x4.shared.b16 {%0,%1,%2,%3}, [%4];"
                 : "=r"(r[0]), "=r"(r[1]), "=r"(r[2]), "=r"(r[3]) : "r"(addr));
}
__device__ __forceinline__ void ldm_x4_trans(uint32_t* r, uint32_t addr) {
    asm volatile("ldmatrix.sync.aligned.m8n8.x4.trans.shared.b16 {%0,%1,%2,%3}, [%4];"
                 : "=r"(r[0]), "=r"(r[1]), "=r"(r[2]), "=r"(r[3]) : "r"(addr));
}
__device__ __forceinline__ void mma_bf16_v(float* d, const uint32_t* a,
                                           uint32_t b0, uint32_t b1) {
    asm volatile(
        "mma.sync.aligned.m16n8k16.row.col.f32.bf16.bf16.f32 "
        "{%0,%1,%2,%3}, {%4,%5,%6,%7}, {%8,%9}, {%0,%1,%2,%3};"
        : "+f"(d[0]), "+f"(d[1]), "+f"(d[2]), "+f"(d[3])
        : "r"(a[0]), "r"(a[1]), "r"(a[2]), "r"(a[3]), "r"(b0), "r"(b1));
}
__device__ __forceinline__ void mma_bf16(float* d, const uint32_t* a,
                                         uint32_t b0, uint32_t b1) {
    asm("mma.sync.aligned.m16n8k16.row.col.f32.bf16.bf16.f32 "
        "{%0,%1,%2,%3}, {%4,%5,%6,%7}, {%8,%9}, {%0,%1,%2,%3};"
        : "+f"(d[0]), "+f"(d[1]), "+f"(d[2]), "+f"(d[3])
        : "r"(a[0]), "r"(a[1]), "r"(a[2]), "r"(a[3]), "r"(b0), "r"(b1));
}
__device__ __forceinline__ uint32_t b2u(__nv_bfloat162 v) {
    return *reinterpret_cast<uint32_t*>(&v);
}
__device__ __forceinline__ void split_pair(float x, float y,
                                           uint32_t& hi, uint32_t& lo) {
    __nv_bfloat162 h = __float22bfloat162_rn(make_float2(x, y));
    float2 hf = __bfloat1622float2(h);
    __nv_bfloat162 l = __float22bfloat162_rn(make_float2(x - hf.x, y - hf.y));
    hi = b2u(h); lo = b2u(l);
}

// ---------------------------------------------------------------------------
// Conversion kernels
// ---------------------------------------------------------------------------
__global__ void split_kernel(const float* __restrict__ in,
                             __nv_bfloat16* __restrict__ hi,
                             __nv_bfloat16* __restrict__ lo, int n)
{
    int i = (blockIdx.x * blockDim.x + threadIdx.x) * 8;
    if (i >= n) return;
    float4 a = *(const float4*)(in + i);
    float4 b = *(const float4*)(in + i + 4);
    float v[8] = {a.x, a.y, a.z, a.w, b.x, b.y, b.z, b.w};
    __nv_bfloat16 h[8], l[8];
#pragma unroll
    for (int j = 0; j < 8; j++) {
        h[j] = __float2bfloat16(v[j]);
        l[j] = __float2bfloat16(v[j] - __bfloat162float(h[j]));
    }
    *(uint4*)(hi + i) = *(uint4*)h;
    *(uint4*)(lo + i) = *(uint4*)l;
}

// W [K][N] row-major -> Wt hi/lo [N][K]
__global__ void transpose_split(const float* __restrict__ W,
                                __nv_bfloat16* __restrict__ Thi,
                                __nv_bfloat16* __restrict__ Tlo,
                                int K, int N)
{
    __shared__ float tile[32][33];
    int k0 = blockIdx.y * 32, n0 = blockIdx.x * 32;
    int tx = threadIdx.x, ty = threadIdx.y;
#pragma unroll
    for (int i = ty; i < 32; i += 8)
        tile[i][tx] = W[(size_t)(k0 + i) * N + n0 + tx];
    __syncthreads();
#pragma unroll
    for (int i = ty; i < 32; i += 8) {
        float v = tile[tx][i];
        __nv_bfloat16 h = __float2bfloat16(v);
        float r = v - __bfloat162float(h);
        Thi[(size_t)(n0 + i) * K + k0 + tx] = h;
        Tlo[(size_t)(n0 + i) * K + k0 + tx] = __float2bfloat16(r);
    }
}

// ---------------------------------------------------------------------------
// mma.sync bf16 split GEMM — 128-thread CTAs, 64x128 tile, BK=16.
// 4 warps (2m x 2n, 32x64 warp tile — per-warp code identical to before).
// Rows padded to 24 bf16 (48B): ldmatrix banks {0,12,24,4,16,28,8,20} x 4
// are conflict-free. Target: 4 independent CTAs/SM for cross-CTA overlap.
// Per-accumulator HH->HL->LH order and K order preserved -> bit-identical.
// ---------------------------------------------------------------------------
#define BK    16
#define PADG  24                     // elements per row (48 bytes)
#define A_MB  (64 * PADG * 2)        // 3072 B per A matrix tile
#define B_MB  (128 * PADG * 2)       // 6144 B per B matrix tile
#define STAGE_B (2 * A_MB + 2 * B_MB)  // 18432
#define GEMM_SMEM (2 * STAGE_B)        // 36864
#define NCHUNK (GK / BK)               // 64

__global__ __launch_bounds__(128) void tc_gemm_mma(
    const __nv_bfloat16* __restrict__ Ah, const __nv_bfloat16* __restrict__ Al,
    const __nv_bfloat16* __restrict__ Bh, const __nv_bfloat16* __restrict__ Bl,
    const float* __restrict__ bias, float* __restrict__ Co,
    __nv_bfloat16* __restrict__ Chi, __nv_bfloat16* __restrict__ Clo,
    int N, int split_out)
{
    extern __shared__ char smem[];
    const uint32_t sb = smem_u32(smem);
    const int tid = threadIdx.x;
    const int wid = tid >> 5, lane = tid & 31;
    const int warp_m = wid >> 1, warp_n = wid & 1;
    const int m0 = blockIdx.y * 64, n0 = blockIdx.x * 128;

    const __nv_bfloat16* aH_g = Ah + (size_t)m0 * GK;
    const __nv_bfloat16* aL_g = Al + (size_t)m0 * GK;
    const __nv_bfloat16* bH_g = Bh + (size_t)n0 * GK;
    const __nv_bfloat16* bL_g = Bl + (size_t)n0 * GK;

    // 768 16B segments per stage: A hi 128, A lo 128, B hi 256, B lo 256.
    auto prefetch = [&](int c, int stage) {
        const int k0 = c * BK;
        const uint32_t so = sb + stage * STAGE_B;
#pragma unroll
        for (int i = 0; i < 6; i++) {
            int idx = tid + i * 128;
            if (idx < 256) {               // A hi / A lo
                int m = idx >> 7;          // 0=hi 1=lo
                int t = idx & 127;
                int r = t >> 1, s = t & 1;
                const __nv_bfloat16* src = (m ? aL_g : aH_g)
                                           + (size_t)r * GK + k0 + s * 8;
                cp_async16(so + (uint32_t)(m * A_MB + r * 48 + s * 16), src);
            } else {                       // B hi / B lo
                int t2 = idx - 256;
                int m = t2 >> 8;           // 0=hi 1=lo
                int t = t2 & 255;
                int r = t >> 1, s = t & 1;
                const __nv_bfloat16* src = (m ? bL_g : bH_g)
                                           + (size_t)r * GK + k0 + s * 8;
                cp_async16(so + (uint32_t)(2 * A_MB + m * B_MB + r * 48 + s * 16), src);
            }
        }
    };

    float acc[2][8][4];
#pragma unroll
    for (int a = 0; a < 2; a++)
#pragma unroll
        for (int b = 0; b < 8; b++)
#pragma unroll
            for (int c = 0; c < 4; c++) acc[a][b][c] = 0.f;

    prefetch(0, 0);
    cp_commit();

    const int a_row = (lane & 15);
    const int a_colb = (lane >> 4) << 4;   // byte offset 0 or 16
    const int b_tile = lane >> 3;
    const int b_rin = lane & 7;
    const int b_nrow = ((b_tile >> 1) << 3) + b_rin;
    const int b_kb = (b_tile & 1) << 4;    // byte offset 0 or 16

    for (int c = 0; c < NCHUNK; c++) {
        const int stage = c & 1;
        if (c + 1 < NCHUNK) { prefetch(c + 1, stage ^ 1); cp_commit(); }
        if (c + 1 < NCHUNK) cp_wait<1>(); else cp_wait<0>();
        __syncthreads();

        const uint32_t so = sb + stage * STAGE_B;
        uint32_t aH[2][4], aL[2][4];
#pragma unroll
        for (int mi = 0; mi < 2; mi++) {
            uint32_t off = (uint32_t)(warp_m * 32 + mi * 16 + a_row) * 48 + a_colb;
            ldm_x4(aH[mi], so + off);
            ldm_x4(aL[mi], so + A_MB + off);
        }
#pragma unroll
        for (int nj = 0; nj < 4; nj++) {
            uint32_t bH[4], bL[4];
            uint32_t off = (uint32_t)(warp_n * 64 + nj * 16 + b_nrow) * 48 + b_kb;
            ldm_x4(bH, so + 2 * A_MB + off);
            ldm_x4(bL, so + 2 * A_MB + B_MB + off);
#pragma unroll
            for (int mi = 0; mi < 2; mi++) {
                mma_bf16_v(acc[mi][nj * 2],     aH[mi], bH[0], bH[1]);
                mma_bf16_v(acc[mi][nj * 2 + 1], aH[mi], bH[2], bH[3]);
                mma_bf16_v(acc[mi][nj * 2],     aH[mi], bL[0], bL[1]);
                mma_bf16_v(acc[mi][nj * 2 + 1], aH[mi], bL[2], bL[3]);
                mma_bf16_v(acc[mi][nj * 2],     aL[mi], bH[0], bH[1]);
                mma_bf16_v(acc[mi][nj * 2 + 1], aL[mi], bH[2], bH[3]);
            }
        }
        __syncthreads();
    }

    const int r_base = m0 + warp_m * 32 + (lane >> 2);
    const int c_base = n0 + warp_n * 64 + (lane & 3) * 2;
    if (split_out) {
#pragma unroll
        for (int mi = 0; mi < 2; mi++) {
#pragma unroll
            for (int nj8 = 0; nj8 < 8; nj8++) {
                int col = c_base + nj8 * 8;
                float b0 = __ldg(bias + col), b1 = __ldg(bias + col + 1);
                int r0 = r_base + mi * 16;
                uint32_t hh, ll;
                split_pair(acc[mi][nj8][0] + b0, acc[mi][nj8][1] + b1, hh, ll);
                *(uint32_t*)(Chi + (size_t)r0 * N + col) = hh;
                *(uint32_t*)(Clo + (size_t)r0 * N + col) = ll;
                split_pair(acc[mi][nj8][2] + b0, acc[mi][nj8][3] + b1, hh, ll);
                *(uint32_t*)(Chi + (size_t)(r0 + 8) * N + col) = hh;
                *(uint32_t*)(Clo + (size_t)(r0 + 8) * N + col) = ll;
            }
        }
    } else {
#pragma unroll
        for (int mi = 0; mi < 2; mi++) {
#pragma unroll
            for (int nj8 = 0; nj8 < 8; nj8++) {
                int col = c_base + nj8 * 8;
                float b0 = __ldg(bias + col), b1 = __ldg(bias + col + 1);
                int r0 = r_base + mi * 16;
                Co[(size_t)r0 * N + col]           = acc[mi][nj8][0] + b0;
                Co[(size_t)r0 * N + col + 1]       = acc[mi][nj8][1] + b1;
                Co[(size_t)(r0 + 8) * N + col]     = acc[mi][nj8][2] + b0;
                Co[(size_t)(r0 + 8) * N + col + 1] = acc[mi][nj8][3] + b1;
            }
        }
    }
}

// ---------------------------------------------------------------------------
// Tensor-core causal flash attention (unchanged from round 9/10).
// ---------------------------------------------------------------------------
#define PADA 72
#define KTB  9216
#define QB   18432
#define KVS  36864
#define KVBASE (2 * QB)
#define FLASH_SMEM (KVBASE + 2 * KVS)   // 110592

__global__ __launch_bounds__(256) void flash_mma_kernel(
    const __nv_bfloat16* __restrict__ qkvh,
    const __nv_bfloat16* __restrict__ qkvl,
    __nv_bfloat16* __restrict__ yhi, __nv_bfloat16* __restrict__ ylo)
{
    extern __shared__ __align__(16) char smem[];
    const uint32_t sb = smem_u32(smem);
    const int tid = threadIdx.x;
    const int wid = tid >> 5, lane = tid & 31;
    const int bh = blockIdx.x, b = bh >> 4, h = bh & 15;
    const int qt = (T_ / 128 - 1) - blockIdx.y;  // long CTAs first
    const int q0 = qt * 128;
    const size_t rowbase = (size_t)b * T_ * C3;

    auto fillKV = [&](int kt, int s) {
        const int k0 = kt * 64;
        const uint32_t so = sb + KVBASE + s * KVS;
#pragma unroll
        for (int i = 0; i < 8; i++) {
            int idx = tid + i * 256;
            int mat = idx >> 9;            // 0=Kh 1=Kl 2=Vh 3=Vl
            int rem = idx & 511;
            int r = rem >> 3, seg = rem & 7;
            const __nv_bfloat16* src =
                ((mat & 1) ? qkvl : qkvh) + rowbase + (size_t)(k0 + r) * C3
                + ((mat >> 1) ? 2 * C_ : C_) + h * D_ + seg * 8;
            cp_async16(so + (uint32_t)(mat * KTB + r * 144 + seg * 16), src);
        }
    };

    // ---- stage Q (unscaled hi/lo; 1/8 applied to scores post-MMA) ----
    {
#pragma unroll
        for (int i = 0; i < 8; i++) {
            int idx = tid + i * 256;       // 0..2047
            int mat = idx >> 10;           // 0=hi 1=lo
            int rem = idx & 1023;
            int r = rem >> 3, seg = rem & 7;
            const __nv_bfloat16* src =
                (mat ? qkvl : qkvh) + rowbase + (size_t)(q0 + r) * C3
                + h * D_ + seg * 8;
            cp_async16(sb + (uint32_t)(mat * QB + r * 144 + seg * 16), src);
        }
    }
    cp_commit();
    fillKV(0, 0);
    cp_commit();

    const int a_row = lane & 15;
    const int a_col8 = (lane >> 4) << 3;
    const int b_tile = lane >> 3;
    const int b_nrow = ((b_tile >> 1) << 3) + (lane & 7);
    const int b_kcol = (b_tile & 1) << 3;
    const int v_krow = ((b_tile & 1) << 3) + (lane & 7);
    const int v_ncol = (b_tile >> 1) << 3;

    cp_wait<1>();      // Q group done (KV0 may still be in flight)
    __syncthreads();

    uint32_t aQh[4][4], aQl[4][4];
#pragma unroll
    for (int ks = 0; ks < 4; ks++) {
        uint32_t off = (uint32_t)((wid * 16 + a_row) * PADA + ks * 16 + a_col8) * 2;
        ldm_x4(aQh[ks], sb + off);
        ldm_x4(aQl[ks], sb + QB + off);
    }

    float oacc[8][4];
#pragma unroll
    for (int i = 0; i < 8; i++)
#pragma unroll
        for (int j = 0; j < 4; j++) oacc[i][j] = 0.f;
    float mrow[2] = {-1e30f, -1e30f};
    float lrow[2] = {0.f, 0.f};

    const int ntiles = 2 * (qt + 1);
    for (int kt = 0; kt < ntiles; kt++) {
        const int s = kt & 1;
        const int k0 = kt * 64;
        __syncthreads();   // all warps done reading stage s^1 (tile kt-1)
        if (kt + 1 < ntiles) { fillKV(kt + 1, s ^ 1); cp_commit(); }
        if (kt + 1 < ntiles) cp_wait<1>(); else cp_wait<0>();
        __syncthreads();   // stage s (tile kt) visible to all

        const uint32_t kvso = sb + KVBASE + s * KVS;

        // ---- S = Q @ K^T (3-pass) ----
        float sacc[8][4];
#pragma unroll
        for (int i = 0; i < 8; i++)
#pragma unroll
            for (int j = 0; j < 4; j++) sacc[i][j] = 0.f;
#pragma unroll
        for (int ks = 0; ks < 4; ks++) {
            uint32_t bH[4], bL[4];
#pragma unroll
            for (int nj = 0; nj < 4; nj++) {
                uint32_t off = (uint32_t)((nj * 16 + b_nrow) * PADA
                                          + ks * 16 + b_kcol) * 2;
                ldm_x4(bH, kvso + off);
                ldm_x4(bL, kvso + KTB + off);
                mma_bf16(sacc[nj * 2],     aQh[ks], bH[0], bH[1]);
                mma_bf16(sacc[nj * 2 + 1], aQh[ks], bH[2], bH[3]);
                mma_bf16(sacc[nj * 2],     aQh[ks], bL[0], bL[1]);
                mma_bf16(sacc[nj * 2 + 1], aQh[ks], bL[2], bL[3]);
                mma_bf16(sacc[nj * 2],     aQl[ks], bH[0], bH[1]);
                mma_bf16(sacc[nj * 2 + 1], aQl[ks], bH[2], bH[3]);
            }
        }
        // apply 1/sqrt(D) = 1/8 (exact pow2; commutes with the bf16 split)
#pragma unroll
        for (int nb = 0; nb < 8; nb++) {
            sacc[nb][0] *= 0.125f; sacc[nb][1] *= 0.125f;
            sacc[nb][2] *= 0.125f; sacc[nb][3] *= 0.125f;
        }

        // ---- causal mask (last two tiles only) ----
        if (k0 >= q0) {
            const int qg = q0 + wid * 16 + (lane >> 2);
            const int cg = k0 + (lane & 3) * 2;
#pragma unroll
            for (int nb = 0; nb < 8; nb++) {
                int col = cg + nb * 8;
                if (col > qg)          sacc[nb][0] = -1e30f;
                if (col + 1 > qg)      sacc[nb][1] = -1e30f;
                if (col > qg + 8)      sacc[nb][2] = -1e30f;
                if (col + 1 > qg + 8)  sacc[nb][3] = -1e30f;
            }
        }

        // ---- online softmax ----
        float mn0 = mrow[0], mn1 = mrow[1];
#pragma unroll
        for (int nb = 0; nb < 8; nb++) {
            mn0 = fmaxf(mn0, fmaxf(sacc[nb][0], sacc[nb][1]));
            mn1 = fmaxf(mn1, fmaxf(sacc[nb][2], sacc[nb][3]));
        }
        mn0 = fmaxf(mn0, __shfl_xor_sync(0xFFFFFFFF, mn0, 1));
        mn0 = fmaxf(mn0, __shfl_xor_sync(0xFFFFFFFF, mn0, 2));
        mn1 = fmaxf(mn1, __shfl_xor_sync(0xFFFFFFFF, mn1, 1));
        mn1 = fmaxf(mn1, __shfl_xor_sync(0xFFFFFFFF, mn1, 2));
        const float corr0 = __expf(mrow[0] - mn0);
        const float corr1 = __expf(mrow[1] - mn1);
        mrow[0] = mn0; mrow[1] = mn1;

        float ps0 = 0.f, ps1 = 0.f;
#pragma unroll
        for (int nb = 0; nb < 8; nb++) {
            sacc[nb][0] = __expf(sacc[nb][0] - mn0);
            sacc[nb][1] = __expf(sacc[nb][1] - mn0);
            sacc[nb][2] = __expf(sacc[nb][2] - mn1);
            sacc[nb][3] = __expf(sacc[nb][3] - mn1);
            ps0 += sacc[nb][0] + sacc[nb][1];
            ps1 += sacc[nb][2] + sacc[nb][3];
        }
        ps0 += __shfl_xor_sync(0xFFFFFFFF, ps0, 1);
        ps0 += __shfl_xor_sync(0xFFFFFFFF, ps0, 2);
        ps1 += __shfl_xor_sync(0xFFFFFFFF, ps1, 1);
        ps1 += __shfl_xor_sync(0xFFFFFFFF, ps1, 2);
        lrow[0] = lrow[0] * corr0 + ps0;
        lrow[1] = lrow[1] * corr1 + ps1;
#pragma unroll
        for (int nb = 0; nb < 8; nb++) {
            oacc[nb][0] *= corr0; oacc[nb][1] *= corr0;
            oacc[nb][2] *= corr1; oacc[nb][3] *= corr1;
        }

        // ---- O += P @ V (3-pass, V via ldmatrix.trans) ----
#pragma unroll
        for (int ks = 0; ks < 4; ks++) {
            uint32_t pH[4], pL[4];
            split_pair(sacc[2 * ks][0],     sacc[2 * ks][1],     pH[0], pL[0]);
            split_pair(sacc[2 * ks][2],     sacc[2 * ks][3],     pH[1], pL[1]);
            split_pair(sacc[2 * ks + 1][0], sacc[2 * ks + 1][1], pH[2], pL[2]);
            split_pair(sacc[2 * ks + 1][2], sacc[2 * ks + 1][3], pH[3], pL[3]);
#pragma unroll
            for (int nj = 0; nj < 4; nj++) {
                uint32_t bH[4], bL[4];
                uint32_t off = (uint32_t)((ks * 16 + v_krow) * PADA
                                          + nj * 16 + v_ncol) * 2;
                ldm_x4_trans(bH, kvso + 2 * KTB + off);
                ldm_x4_trans(bL, kvso + 3 * KTB + off);
                mma_bf16(oacc[nj * 2],     pH, bH[0], bH[1]);
                mma_bf16(oacc[nj * 2 + 1], pH, bH[2], bH[3]);
                mma_bf16(oacc[nj * 2],     pH, bL[0], bL[1]);
                mma_bf16(oacc[nj * 2 + 1], pH, bL[2], bL[3]);
                mma_bf16(oacc[nj * 2],     pL, bH[0], bH[1]);
                mma_bf16(oacc[nj * 2 + 1], pL, bH[2], bH[3]);
            }
        }
    }

    // ---- normalize and write y as bf16 hi/lo (fused split) ----
    const float inv0 = 1.f / lrow[0];
    const float inv1 = 1.f / lrow[1];
    const int rg = q0 + wid * 16 + (lane >> 2);
    const size_t e0 = ((size_t)b * T_ + rg) * C_ + h * D_ + (lane & 3) * 2;
#pragma unroll
    for (int nb = 0; nb < 8; nb++) {
        uint32_t h0, l0, h1, l1;
        split_pair(oacc[nb][0] * inv0, oacc[nb][1] * inv0, h0, l0);
        split_pair(oacc[nb][2] * inv1, oacc[nb][3] * inv1, h1, l1);
        *(uint32_t*)(yhi + e0 + nb * 8)          = h0;
        *(uint32_t*)(ylo + e0 + nb * 8)          = l0;
        *(uint32_t*)(yhi + e0 + 8 * C_ + nb * 8) = h1;
        *(uint32_t*)(ylo + e0 + 8 * C_ + nb * 8) = l1;
    }
}

// ---------------------------------------------------------------------------
extern "C" void kernel_launch(void* const* d_in, const int* in_sizes, int n_in,
                              void* d_out, int out_size)
{
    const float* x      = (const float*)d_in[0];
    const float* W_attn = (const float*)d_in[1];
    const float* b_attn = (const float*)d_in[2];
    const float* W_proj = (const float*)d_in[3];
    const float* b_proj = (const float*)d_in[4];
    float* out = (float*)d_out;

    __nv_bfloat16 *qkvh, *qkvl, *xhi, *xlo, *yhi, *ylo, *wahi, *walo, *wphi, *wplo;
    cudaGetSymbolAddress((void**)&qkvh, g_qkvh);
    cudaGetSymbolAddress((void**)&qkvl, g_qkvl);
    cudaGetSymbolAddress((void**)&xhi, g_xhi);
    cudaGetSymbolAddress((void**)&xlo, g_xlo);
    cudaGetSymbolAddress((void**)&yhi, g_yhi);
    cudaGetSymbolAddress((void**)&ylo, g_ylo);
    cudaGetSymbolAddress((void**)&wahi, g_wahi);
    cudaGetSymbolAddress((void**)&walo, g_walo);
    cudaGetSymbolAddress((void**)&wphi, g_wphi);
    cudaGetSymbolAddress((void**)&wplo, g_wplo);

    cudaFuncSetAttribute(tc_gemm_mma, cudaFuncAttributeMaxDynamicSharedMemorySize,
                         GEMM_SMEM);
    cudaFuncSetAttribute(flash_mma_kernel,
                         cudaFuncAttributeMaxDynamicSharedMemorySize, FLASH_SMEM);

    const int NTOK_EL = M_TOK * C_;

    // 1) split x -> bf16 hi/lo
    split_kernel<<<NTOK_EL / 8 / 256, 256>>>(x, xhi, xlo, NTOK_EL);
    // 2) transpose+split weights
    transpose_split<<<dim3(C3 / 32, C_ / 32), dim3(32, 8)>>>(W_attn, wahi, walo, C_, C3);
    transpose_split<<<dim3(C_ / 32, C_ / 32), dim3(32, 8)>>>(W_proj, wphi, wplo, C_, C_);
    // 3) QKV GEMM -> qkv bf16 hi/lo (split fused in epilogue)
    tc_gemm_mma<<<dim3(C3 / 128, M_TOK / 64), 128, GEMM_SMEM>>>(
        xhi, xlo, wahi, walo, b_attn, nullptr, qkvh, qkvl, C3, 1);
    // 4) causal flash attention (cp.async staging, double-buffered KV)
    flash_mma_kernel<<<dim3(B_ * H_, T_ / 128), 256, FLASH_SMEM>>>(
        qkvh, qkvl, yhi, ylo);
    // 5) proj GEMM -> d_out (fp32)
    tc_gemm_mma<<<dim3(C_ / 128, M_TOK / 64), 128, GEMM_SMEM>>>(
        yhi, ylo, wphi, wplo, b_proj, out, nullptr, nullptr, C_, 0);
}

// round 12
// speedup vs baseline: 1.0806x; 1.0806x over previous
#include <cuda_runtime.h>
#include <cuda_bf16.h>
#include <cstdint>
#include <cstddef>

// Problem constants
#define B_  4
#define T_  2048
#define C_  1024
#define H_  16
#define D_  64
#define M_TOK (B_ * T_)      // 8192
#define C3 (3 * C_)          // 3072
#define GK 1024              // K of both GEMMs

// ---------------------------------------------------------------------------
// Scratch (device globals; allocation in kernel_launch is forbidden)
// ---------------------------------------------------------------------------
__device__ __nv_bfloat16 g_qkvh[(size_t)M_TOK * C3]; // qkv hi (from GEMM epi)
__device__ __nv_bfloat16 g_qkvl[(size_t)M_TOK * C3]; // qkv lo
__device__ __nv_bfloat16 g_xhi[(size_t)M_TOK * C_];
__device__ __nv_bfloat16 g_xlo[(size_t)M_TOK * C_];
__device__ __nv_bfloat16 g_yhi[(size_t)M_TOK * C_];
__device__ __nv_bfloat16 g_ylo[(size_t)M_TOK * C_];
__device__ __nv_bfloat16 g_wahi[(size_t)C3 * C_];  // W_attn^T [3C][C]
__device__ __nv_bfloat16 g_walo[(size_t)C3 * C_];
__device__ __nv_bfloat16 g_wphi[(size_t)C_ * C_];  // W_proj^T [C][C]
__device__ __nv_bfloat16 g_wplo[(size_t)C_ * C_];

// ---------------------------------------------------------------------------
// PTX helpers
// ---------------------------------------------------------------------------
__device__ __forceinline__ uint32_t smem_u32(const void* p) {
    uint32_t a;
    asm("{ .reg .u64 t; cvta.to.shared.u64 t, %1; cvt.u32.u64 %0, t; }"
        : "=r"(a) : "l"(p));
    return a;
}
__device__ __forceinline__ void cp_async16(uint32_t dst, const void* src) {
    asm volatile("cp.async.cg.shared.global [%0], [%1], 16;"
                 :: "r"(dst), "l"(src) : "memory");
}
__device__ __forceinline__ void cp_commit() {
    asm volatile("cp.async.commit_group;" ::: "memory");
}
template <int N>
__device__ __forceinline__ void cp_wait() {
    asm volatile("cp.async.wait_group %0;" :: "n"(N) : "memory");
}
__device__ __forceinline__ void ldm_x4(uint32_t* r, uint32_t addr) {
    asm volatile("ldmatrix.sync.aligned.m8n8.x4.shared.b16 {%0,%1,%2,%3}, [%4];"
                 : "=r"(r[0]), "=r"(r[1]), "=r"(r[2]), "=r"(r[3]) : "r"(addr));
}
__device__ __forceinline__ void ldm_x4_trans(uint32_t* r, uint32_t addr) {
    asm volatile("ldmatrix.sync.aligned.m8n8.x4.trans.shared.b16 {%0,%1,%2,%3}, [%4];"
                 : "=r"(r[0]), "=r"(r[1]), "=r"(r[2]), "=r"(r[3]) : "r"(addr));
}
__device__ __forceinline__ void mma_bf16_v(float* d, const uint32_t* a,
                                           uint32_t b0, uint32_t b1) {
    asm volatile(
        "mma.sync.aligned.m16n8k16.row.col.f32.bf16.bf16.f32 "
        "{%0,%1,%2,%3}, {%4,%5,%6,%7}, {%8,%9}, {%0,%1,%2,%3};"
        : "+f"(d[0]), "+f"(d[1]), "+f"(d[2]), "+f"(d[3])
        : "r"(a[0]), "r"(a[1]), "r"(a[2]), "r"(a[3]), "r"(b0), "r"(b1));
}
__device__ __forceinline__ void mma_bf16(float* d, const uint32_t* a,
                                         uint32_t b0, uint32_t b1) {
    asm("mma.sync.aligned.m16n8k16.row.col.f32.bf16.bf16.f32 "
        "{%0,%1,%2,%3}, {%4,%5,%6,%7}, {%8,%9}, {%0,%1,%2,%3};"
        : "+f"(d[0]), "+f"(d[1]), "+f"(d[2]), "+f"(d[3])
        : "r"(a[0]), "r"(a[1]), "r"(a[2]), "r"(a[3]), "r"(b0), "r"(b1));
}
__device__ __forceinline__ uint32_t b2u(__nv_bfloat162 v) {
    return *reinterpret_cast<uint32_t*>(&v);
}
__device__ __forceinline__ void split_pair(float x, float y,
                                           uint32_t& hi, uint32_t& lo) {
    __nv_bfloat162 h = __float22bfloat162_rn(make_float2(x, y));
    float2 hf = __bfloat1622float2(h);
    __nv_bfloat162 l = __float22bfloat162_rn(make_float2(x - hf.x, y - hf.y));
    hi = b2u(h); lo = b2u(l);
}

// ---------------------------------------------------------------------------
// Conversion kernels
// ---------------------------------------------------------------------------
__global__ void split_kernel(const float* __restrict__ in,
                             __nv_bfloat16* __restrict__ hi,
                             __nv_bfloat16* __restrict__ lo, int n)
{
    int i = (blockIdx.x * blockDim.x + threadIdx.x) * 8;
    if (i >= n) return;
    float4 a = *(const float4*)(in + i);
    float4 b = *(const float4*)(in + i + 4);
    float v[8] = {a.x, a.y, a.z, a.w, b.x, b.y, b.z, b.w};
    __nv_bfloat16 h[8], l[8];
#pragma unroll
    for (int j = 0; j < 8; j++) {
        h[j] = __float2bfloat16(v[j]);
        l[j] = __float2bfloat16(v[j] - __bfloat162float(h[j]));
    }
    *(uint4*)(hi + i) = *(uint4*)h;
    *(uint4*)(lo + i) = *(uint4*)l;
}

// W [K][N] row-major -> Wt hi/lo [N][K]
__global__ void transpose_split(const float* __restrict__ W,
                                __nv_bfloat16* __restrict__ Thi,
                                __nv_bfloat16* __restrict__ Tlo,
                                int K, int N)
{
    __shared__ float tile[32][33];
    int k0 = blockIdx.y * 32, n0 = blockIdx.x * 32;
    int tx = threadIdx.x, ty = threadIdx.y;
#pragma unroll
    for (int i = ty; i < 32; i += 8)
        tile[i][tx] = W[(size_t)(k0 + i) * N + n0 + tx];
    __syncthreads();
#pragma unroll
    for (int i = ty; i < 32; i += 8) {
        float v = tile[tx][i];
        __nv_bfloat16 h = __float2bfloat16(v);
        float r = v - __bfloat162float(h);
        Thi[(size_t)(n0 + i) * K + k0 + tx] = h;
        Tlo[(size_t)(n0 + i) * K + k0 + tx] = __float2bfloat16(r);
    }
}

// ---------------------------------------------------------------------------
// mma.sync bf16 split GEMM — EXACT round-10 version (496 us QKV, 2 CTAs/SM).
// ---------------------------------------------------------------------------
#define PAD 40
#define MAT_EL (128 * PAD)
#define MAT_B (MAT_EL * 2)
#define STAGE_B (4 * MAT_B)
#define GEMM_SMEM (2 * STAGE_B)
#define NCHUNK (GK / 32)

__global__ __launch_bounds__(256) void tc_gemm_mma(
    const __nv_bfloat16* __restrict__ Ah, const __nv_bfloat16* __restrict__ Al,
    const __nv_bfloat16* __restrict__ Bh, const __nv_bfloat16* __restrict__ Bl,
    const float* __restrict__ bias, float* __restrict__ Co,
    __nv_bfloat16* __restrict__ Chi, __nv_bfloat16* __restrict__ Clo,
    int N, int split_out)
{
    extern __shared__ char smem[];
    const uint32_t sb = smem_u32(smem);
    const int tid = threadIdx.x;
    const int wid = tid >> 5, lane = tid & 31;
    const int warp_m = wid >> 1, warp_n = wid & 1;
    const int m0 = blockIdx.y * 128, n0 = blockIdx.x * 128;

    const __nv_bfloat16* srcs[4] = {
        Ah + (size_t)m0 * GK, Al + (size_t)m0 * GK,
        Bh + (size_t)n0 * GK, Bl + (size_t)n0 * GK };

    auto prefetch = [&](int c, int stage) {
        const int k0 = c * 32;
        const uint32_t so = sb + stage * STAGE_B;
#pragma unroll
        for (int msel = 0; msel < 4; msel++) {
#pragma unroll
            for (int i = 0; i < 2; i++) {
                int idx = tid + i * 256;
                int r = idx >> 2, seg = idx & 3;
                uint32_t dst = so + msel * MAT_B + (uint32_t)(r * PAD + seg * 8) * 2;
                cp_async16(dst, srcs[msel] + (size_t)r * GK + k0 + seg * 8);
            }
        }
    };

    float acc[2][8][4];
#pragma unroll
    for (int a = 0; a < 2; a++)
#pragma unroll
        for (int b = 0; b < 8; b++)
#pragma unroll
            for (int c = 0; c < 4; c++) acc[a][b][c] = 0.f;

    prefetch(0, 0);
    cp_commit();

    const int a_row = (lane & 15);
    const int a_col8 = (lane >> 4) << 3;
    const int b_tile = lane >> 3;
    const int b_rin = lane & 7;
    const int b_nrow = ((b_tile >> 1) << 3) + b_rin;
    const int b_kcol = (b_tile & 1) << 3;

    for (int c = 0; c < NCHUNK; c++) {
        const int stage = c & 1;
        if (c + 1 < NCHUNK) { prefetch(c + 1, stage ^ 1); cp_commit(); }
        if (c + 1 < NCHUNK) cp_wait<1>(); else cp_wait<0>();
        __syncthreads();

        const uint32_t so = sb + stage * STAGE_B;
#pragma unroll
        for (int ks = 0; ks < 2; ks++) {
            uint32_t aH[2][4], aL[2][4];
#pragma unroll
            for (int mi = 0; mi < 2; mi++) {
                uint32_t off = (uint32_t)((warp_m * 32 + mi * 16 + a_row) * PAD
                                          + ks * 16 + a_col8) * 2;
                ldm_x4(aH[mi], so + 0 * MAT_B + off);
                ldm_x4(aL[mi], so + 1 * MAT_B + off);
            }
#pragma unroll
            for (int nj = 0; nj < 4; nj++) {
                uint32_t bH[4], bL[4];
                uint32_t off = (uint32_t)((warp_n * 64 + nj * 16 + b_nrow) * PAD
                                          + ks * 16 + b_kcol) * 2;
                ldm_x4(bH, so + 2 * MAT_B + off);
                ldm_x4(bL, so + 3 * MAT_B + off);
#pragma unroll
                for (int mi = 0; mi < 2; mi++) {
                    mma_bf16_v(acc[mi][nj * 2],     aH[mi], bH[0], bH[1]);
                    mma_bf16_v(acc[mi][nj * 2 + 1], aH[mi], bH[2], bH[3]);
                    mma_bf16_v(acc[mi][nj * 2],     aH[mi], bL[0], bL[1]);
                    mma_bf16_v(acc[mi][nj * 2 + 1], aH[mi], bL[2], bL[3]);
                    mma_bf16_v(acc[mi][nj * 2],     aL[mi], bH[0], bH[1]);
                    mma_bf16_v(acc[mi][nj * 2 + 1], aL[mi], bH[2], bH[3]);
                }
            }
        }
        __syncthreads();
    }

    const int r_base = m0 + warp_m * 32 + (lane >> 2);
    const int c_base = n0 + warp_n * 64 + (lane & 3) * 2;
    if (split_out) {
#pragma unroll
        for (int mi = 0; mi < 2; mi++) {
#pragma unroll
            for (int nj8 = 0; nj8 < 8; nj8++) {
                int col = c_base + nj8 * 8;
                float b0 = __ldg(bias + col), b1 = __ldg(bias + col + 1);
                int r0 = r_base + mi * 16;
                uint32_t hh, ll;
                split_pair(acc[mi][nj8][0] + b0, acc[mi][nj8][1] + b1, hh, ll);
                *(uint32_t*)(Chi + (size_t)r0 * N + col) = hh;
                *(uint32_t*)(Clo + (size_t)r0 * N + col) = ll;
                split_pair(acc[mi][nj8][2] + b0, acc[mi][nj8][3] + b1, hh, ll);
                *(uint32_t*)(Chi + (size_t)(r0 + 8) * N + col) = hh;
                *(uint32_t*)(Clo + (size_t)(r0 + 8) * N + col) = ll;
            }
        }
    } else {
#pragma unroll
        for (int mi = 0; mi < 2; mi++) {
#pragma unroll
            for (int nj8 = 0; nj8 < 8; nj8++) {
                int col = c_base + nj8 * 8;
                float b0 = __ldg(bias + col), b1 = __ldg(bias + col + 1);
                int r0 = r_base + mi * 16;
                Co[(size_t)r0 * N + col]           = acc[mi][nj8][0] + b0;
                Co[(size_t)r0 * N + col + 1]       = acc[mi][nj8][1] + b1;
                Co[(size_t)(r0 + 8) * N + col]     = acc[mi][nj8][2] + b0;
                Co[(size_t)(r0 + 8) * N + col + 1] = acc[mi][nj8][3] + b1;
            }
        }
    }
}

// ---------------------------------------------------------------------------
// Tensor-core causal flash attention.
// Changes vs round 10: single barrier per KV tile ({wait; sync; fill; compute}
// — at the sync all warps finished reading stage s^1, so overwriting it is
// safe), and per-warp causal skip of fully-masked MMA blocks in the two
// diagonal tiles (skipped blocks only feed entries later masked to -1e30, or
// add exact zeros via P=0 — bit-identical results).
// ---------------------------------------------------------------------------
#define PADA 72
#define KTB  9216
#define QB   18432
#define KVS  36864
#define KVBASE (2 * QB)
#define FLASH_SMEM (KVBASE + 2 * KVS)   // 110592

__global__ __launch_bounds__(256) void flash_mma_kernel(
    const __nv_bfloat16* __restrict__ qkvh,
    const __nv_bfloat16* __restrict__ qkvl,
    __nv_bfloat16* __restrict__ yhi, __nv_bfloat16* __restrict__ ylo)
{
    extern __shared__ __align__(16) char smem[];
    const uint32_t sb = smem_u32(smem);
    const int tid = threadIdx.x;
    const int wid = tid >> 5, lane = tid & 31;
    const int bh = blockIdx.x, b = bh >> 4, h = bh & 15;
    const int qt = (T_ / 128 - 1) - blockIdx.y;  // long CTAs first
    const int q0 = qt * 128;
    const size_t rowbase = (size_t)b * T_ * C3;
    const int wqmax = q0 + wid * 16 + 15;  // highest query row this warp owns

    auto fillKV = [&](int kt, int s) {
        const int k0 = kt * 64;
        const uint32_t so = sb + KVBASE + s * KVS;
#pragma unroll
        for (int i = 0; i < 8; i++) {
            int idx = tid + i * 256;
            int mat = idx >> 9;            // 0=Kh 1=Kl 2=Vh 3=Vl
            int rem = idx & 511;
            int r = rem >> 3, seg = rem & 7;
            const __nv_bfloat16* src =
                ((mat & 1) ? qkvl : qkvh) + rowbase + (size_t)(k0 + r) * C3
                + ((mat >> 1) ? 2 * C_ : C_) + h * D_ + seg * 8;
            cp_async16(so + (uint32_t)(mat * KTB + r * 144 + seg * 16), src);
        }
    };

    // ---- stage Q (unscaled hi/lo; 1/8 applied to scores post-MMA) ----
    {
#pragma unroll
        for (int i = 0; i < 8; i++) {
            int idx = tid + i * 256;       // 0..2047
            int mat = idx >> 10;           // 0=hi 1=lo
            int rem = idx & 1023;
            int r = rem >> 3, seg = rem & 7;
            const __nv_bfloat16* src =
                (mat ? qkvl : qkvh) + rowbase + (size_t)(q0 + r) * C3
                + h * D_ + seg * 8;
            cp_async16(sb + (uint32_t)(mat * QB + r * 144 + seg * 16), src);
        }
    }
    cp_commit();
    fillKV(0, 0);
    cp_commit();

    const int a_row = lane & 15;
    const int a_col8 = (lane >> 4) << 3;
    const int b_tile = lane >> 3;
    const int b_nrow = ((b_tile >> 1) << 3) + (lane & 7);
    const int b_kcol = (b_tile & 1) << 3;
    const int v_krow = ((b_tile & 1) << 3) + (lane & 7);
    const int v_ncol = (b_tile >> 1) << 3;

    cp_wait<1>();      // Q group done (KV0 may still be in flight)
    __syncthreads();

    uint32_t aQh[4][4], aQl[4][4];
#pragma unroll
    for (int ks = 0; ks < 4; ks++) {
        uint32_t off = (uint32_t)((wid * 16 + a_row) * PADA + ks * 16 + a_col8) * 2;
        ldm_x4(aQh[ks], sb + off);
        ldm_x4(aQl[ks], sb + QB + off);
    }

    float oacc[8][4];
#pragma unroll
    for (int i = 0; i < 8; i++)
#pragma unroll
        for (int j = 0; j < 4; j++) oacc[i][j] = 0.f;
    float mrow[2] = {-1e30f, -1e30f};
    float lrow[2] = {0.f, 0.f};

    const int ntiles = 2 * (qt + 1);
    for (int kt = 0; kt < ntiles; kt++) {
        const int s = kt & 1;
        const int k0 = kt * 64;
        cp_wait<0>();      // this tile's KV (and everything earlier) complete
        __syncthreads();   // visible to all; all warps done reading stage s^1
        if (kt + 1 < ntiles) { fillKV(kt + 1, s ^ 1); cp_commit(); }

        const uint32_t kvso = sb + KVBASE + s * KVS;

        // ---- S = Q @ K^T (3-pass); skip key-blocks fully above the causal
        //      boundary for this warp's rows ----
        float sacc[8][4];
#pragma unroll
        for (int i = 0; i < 8; i++)
#pragma unroll
            for (int j = 0; j < 4; j++) sacc[i][j] = 0.f;
#pragma unroll
        for (int ks = 0; ks < 4; ks++) {
            uint32_t bH[4], bL[4];
#pragma unroll
            for (int nj = 0; nj < 4; nj++) {
                if (k0 + nj * 16 > wqmax) continue;  // fully masked block
                uint32_t off = (uint32_t)((nj * 16 + b_nrow) * PADA
                                          + ks * 16 + b_kcol) * 2;
                ldm_x4(bH, kvso + off);
                ldm_x4(bL, kvso + KTB + off);
                mma_bf16(sacc[nj * 2],     aQh[ks], bH[0], bH[1]);
                mma_bf16(sacc[nj * 2 + 1], aQh[ks], bH[2], bH[3]);
                mma_bf16(sacc[nj * 2],     aQh[ks], bL[0], bL[1]);
                mma_bf16(sacc[nj * 2 + 1], aQh[ks], bL[2], bL[3]);
                mma_bf16(sacc[nj * 2],     aQl[ks], bH[0], bH[1]);
                mma_bf16(sacc[nj * 2 + 1], aQl[ks], bH[2], bH[3]);
            }
        }
        // apply 1/sqrt(D) = 1/8 (exact pow2; commutes with the bf16 split)
#pragma unroll
        for (int nb = 0; nb < 8; nb++) {
            sacc[nb][0] *= 0.125f; sacc[nb][1] *= 0.125f;
            sacc[nb][2] *= 0.125f; sacc[nb][3] *= 0.125f;
        }

        // ---- causal mask (last two tiles only) ----
        if (k0 >= q0) {
            const int qg = q0 + wid * 16 + (lane >> 2);
            const int cg = k0 + (lane & 3) * 2;
#pragma unroll
            for (int nb = 0; nb < 8; nb++) {
                int col = cg + nb * 8;
                if (col > qg)          sacc[nb][0] = -1e30f;
                if (col + 1 > qg)      sacc[nb][1] = -1e30f;
                if (col > qg + 8)      sacc[nb][2] = -1e30f;
                if (col + 1 > qg + 8)  sacc[nb][3] = -1e30f;
            }
        }

        // ---- online softmax ----
        float mn0 = mrow[0], mn1 = mrow[1];
#pragma unroll
        for (int nb = 0; nb < 8; nb++) {
            mn0 = fmaxf(mn0, fmaxf(sacc[nb][0], sacc[nb][1]));
            mn1 = fmaxf(mn1, fmaxf(sacc[nb][2], sacc[nb][3]));
        }
        mn0 = fmaxf(mn0, __shfl_xor_sync(0xFFFFFFFF, mn0, 1));
        mn0 = fmaxf(mn0, __shfl_xor_sync(0xFFFFFFFF, mn0, 2));
        mn1 = fmaxf(mn1, __shfl_xor_sync(0xFFFFFFFF, mn1, 1));
        mn1 = fmaxf(mn1, __shfl_xor_sync(0xFFFFFFFF, mn1, 2));
        const float corr0 = __expf(mrow[0] - mn0);
        const float corr1 = __expf(mrow[1] - mn1);
        mrow[0] = mn0; mrow[1] = mn1;

        float ps0 = 0.f, ps1 = 0.f;
#pragma unroll
        for (int nb = 0; nb < 8; nb++) {
            sacc[nb][0] = __expf(sacc[nb][0] - mn0);
            sacc[nb][1] = __expf(sacc[nb][1] - mn0);
            sacc[nb][2] = __expf(sacc[nb][2] - mn1);
            sacc[nb][3] = __expf(sacc[nb][3] - mn1);
            ps0 += sacc[nb][0] + sacc[nb][1];
            ps1 += sacc[nb][2] + sacc[nb][3];
        }
        ps0 += __shfl_xor_sync(0xFFFFFFFF, ps0, 1);
        ps0 += __shfl_xor_sync(0xFFFFFFFF, ps0, 2);
        ps1 += __shfl_xor_sync(0xFFFFFFFF, ps1, 1);
        ps1 += __shfl_xor_sync(0xFFFFFFFF, ps1, 2);
        lrow[0] = lrow[0] * corr0 + ps0;
        lrow[1] = lrow[1] * corr1 + ps1;
#pragma unroll
        for (int nb = 0; nb < 8; nb++) {
            oacc[nb][0] *= corr0; oacc[nb][1] *= corr0;
            oacc[nb][2] *= corr1; oacc[nb][3] *= corr1;
        }

        // ---- O += P @ V (3-pass); skip key-groups where P is entirely
        //      zero for this warp (exp of fully-masked block) ----
#pragma unroll
        for (int ks = 0; ks < 4; ks++) {
            if (k0 + ks * 16 > wqmax) continue;  // P block is exactly zero
            uint32_t pH[4], pL[4];
            split_pair(sacc[2 * ks][0],     sacc[2 * ks][1],     pH[0], pL[0]);
            split_pair(sacc[2 * ks][2],     sacc[2 * ks][3],     pH[1], pL[1]);
            split_pair(sacc[2 * ks + 1][0], sacc[2 * ks + 1][1], pH[2], pL[2]);
            split_pair(sacc[2 * ks + 1][2], sacc[2 * ks + 1][3], pH[3], pL[3]);
#pragma unroll
            for (int nj = 0; nj < 4; nj++) {
                uint32_t bH[4], bL[4];
                uint32_t off = (uint32_t)((ks * 16 + v_krow) * PADA
                                          + nj * 16 + v_ncol) * 2;
                ldm_x4_trans(bH, kvso + 2 * KTB + off);
                ldm_x4_trans(bL, kvso + 3 * KTB + off);
                mma_bf16(oacc[nj * 2],     pH, bH[0], bH[1]);
                mma_bf16(oacc[nj * 2 + 1], pH, bH[2], bH[3]);
                mma_bf16(oacc[nj * 2],     pH, bL[0], bL[1]);
                mma_bf16(oacc[nj * 2 + 1], pH, bL[2], bL[3]);
                mma_bf16(oacc[nj * 2],     pL, bH[0], bH[1]);
                mma_bf16(oacc[nj * 2 + 1], pL, bH[2], bH[3]);
            }
        }
    }

    // ---- normalize and write y as bf16 hi/lo (fused split) ----
    const float inv0 = 1.f / lrow[0];
    const float inv1 = 1.f / lrow[1];
    const int rg = q0 + wid * 16 + (lane >> 2);
    const size_t e0 = ((size_t)b * T_ + rg) * C_ + h * D_ + (lane & 3) * 2;
#pragma unroll
    for (int nb = 0; nb < 8; nb++) {
        uint32_t h0, l0, h1, l1;
        split_pair(oacc[nb][0] * inv0, oacc[nb][1] * inv0, h0, l0);
        split_pair(oacc[nb][2] * inv1, oacc[nb][3] * inv1, h1, l1);
        *(uint32_t*)(yhi + e0 + nb * 8)          = h0;
        *(uint32_t*)(ylo + e0 + nb * 8)          = l0;
        *(uint32_t*)(yhi + e0 + 8 * C_ + nb * 8) = h1;
        *(uint32_t*)(ylo + e0 + 8 * C_ + nb * 8) = l1;
    }
}

// ---------------------------------------------------------------------------
extern "C" void kernel_launch(void* const* d_in, const int* in_sizes, int n_in,
                              void* d_out, int out_size)
{
    const float* x      = (const float*)d_in[0];
    const float* W_attn = (const float*)d_in[1];
    const float* b_attn = (const float*)d_in[2];
    const float* W_proj = (const float*)d_in[3];
    const float* b_proj = (const float*)d_in[4];
    float* out = (float*)d_out;

    __nv_bfloat16 *qkvh, *qkvl, *xhi, *xlo, *yhi, *ylo, *wahi, *walo, *wphi, *wplo;
    cudaGetSymbolAddress((void**)&qkvh, g_qkvh);
    cudaGetSymbolAddress((void**)&qkvl, g_qkvl);
    cudaGetSymbolAddress((void**)&xhi, g_xhi);
    cudaGetSymbolAddress((void**)&xlo, g_xlo);
    cudaGetSymbolAddress((void**)&yhi, g_yhi);
    cudaGetSymbolAddress((void**)&ylo, g_ylo);
    cudaGetSymbolAddress((void**)&wahi, g_wahi);
    cudaGetSymbolAddress((void**)&walo, g_walo);
    cudaGetSymbolAddress((void**)&wphi, g_wphi);
    cudaGetSymbolAddress((void**)&wplo, g_wplo);

    cudaFuncSetAttribute(tc_gemm_mma, cudaFuncAttributeMaxDynamicSharedMemorySize,
                         GEMM_SMEM);
    cudaFuncSetAttribute(flash_mma_kernel,
                         cudaFuncAttributeMaxDynamicSharedMemorySize, FLASH_SMEM);

    const int NTOK_EL = M_TOK * C_;

    // 1) split x -> bf16 hi/lo
    split_kernel<<<NTOK_EL / 8 / 256, 256>>>(x, xhi, xlo, NTOK_EL);
    // 2) transpose+split weights
    transpose_split<<<dim3(C3 / 32, C_ / 32), dim3(32, 8)>>>(W_attn, wahi, walo, C_, C3);
    transpose_split<<<dim3(C_ / 32, C_ / 32), dim3(32, 8)>>>(W_proj, wphi, wplo, C_, C_);
    // 3) QKV GEMM -> qkv bf16 hi/lo (split fused in epilogue)
    tc_gemm_mma<<<dim3(C3 / 128, M_TOK / 128), 256, GEMM_SMEM>>>(
        xhi, xlo, wahi, walo, b_attn, nullptr, qkvh, qkvl, C3, 1);
    // 4) causal flash attention (cp.async staging, double-buffered KV)
    flash_mma_kernel<<<dim3(B_ * H_, T_ / 128), 256, FLASH_SMEM>>>(
        qkvh, qkvl, yhi, ylo);
    // 5) proj GEMM -> d_out (fp32)
    tc_gemm_mma<<<dim3(C_ / 128, M_TOK / 128), 256, GEMM_SMEM>>>(
        yhi, ylo, wphi, wplo, b_proj, out, nullptr, nullptr, C_, 0);
}

// round 13
// speedup vs baseline: 1.4299x; 1.3233x over previous
#include <cuda_runtime.h>
#include <cuda_bf16.h>
#include <cuda_fp16.h>
#include <cstdint>
#include <cstddef>

// Problem constants
#define B_  4
#define T_  2048
#define C_  1024
#define H_  16
#define D_  64
#define M_TOK (B_ * T_)      // 8192
#define C3 (3 * C_)          // 3072
#define GK 1024              // K of both GEMMs

// ---------------------------------------------------------------------------
// Scratch (device globals; allocation in kernel_launch is forbidden)
// ---------------------------------------------------------------------------
__device__ __half g_qkvf[(size_t)M_TOK * C3];        // qkv fp16 (from GEMM epi)
__device__ __nv_bfloat16 g_xhi[(size_t)M_TOK * C_];
__device__ __nv_bfloat16 g_xlo[(size_t)M_TOK * C_];
__device__ __nv_bfloat16 g_yhi[(size_t)M_TOK * C_];
__device__ __nv_bfloat16 g_ylo[(size_t)M_TOK * C_];
__device__ __nv_bfloat16 g_wahi[(size_t)C3 * C_];    // W_attn^T [3C][C]
__device__ __nv_bfloat16 g_walo[(size_t)C3 * C_];
__device__ __nv_bfloat16 g_wphi[(size_t)C_ * C_];    // W_proj^T [C][C]
__device__ __nv_bfloat16 g_wplo[(size_t)C_ * C_];

// ---------------------------------------------------------------------------
// PTX helpers
// ---------------------------------------------------------------------------
__device__ __forceinline__ uint32_t smem_u32(const void* p) {
    uint32_t a;
    asm("{ .reg .u64 t; cvta.to.shared.u64 t, %1; cvt.u32.u64 %0, t; }"
        : "=r"(a) : "l"(p));
    return a;
}
__device__ __forceinline__ void cp_async16(uint32_t dst, const void* src) {
    asm volatile("cp.async.cg.shared.global [%0], [%1], 16;"
                 :: "r"(dst), "l"(src) : "memory");
}
__device__ __forceinline__ void cp_commit() {
    asm volatile("cp.async.commit_group;" ::: "memory");
}
template <int N>
__device__ __forceinline__ void cp_wait() {
    asm volatile("cp.async.wait_group %0;" :: "n"(N) : "memory");
}
__device__ __forceinline__ void ldm_x4(uint32_t* r, uint32_t addr) {
    asm volatile("ldmatrix.sync.aligned.m8n8.x4.shared.b16 {%0,%1,%2,%3}, [%4];"
                 : "=r"(r[0]), "=r"(r[1]), "=r"(r[2]), "=r"(r[3]) : "r"(addr));
}
__device__ __forceinline__ void ldm_x4_trans(uint32_t* r, uint32_t addr) {
    asm volatile("ldmatrix.sync.aligned.m8n8.x4.trans.shared.b16 {%0,%1,%2,%3}, [%4];"
                 : "=r"(r[0]), "=r"(r[1]), "=r"(r[2]), "=r"(r[3]) : "r"(addr));
}
__device__ __forceinline__ void mma_bf16_v(float* d, const uint32_t* a,
                                           uint32_t b0, uint32_t b1) {
    asm volatile(
        "mma.sync.aligned.m16n8k16.row.col.f32.bf16.bf16.f32 "
        "{%0,%1,%2,%3}, {%4,%5,%6,%7}, {%8,%9}, {%0,%1,%2,%3};"
        : "+f"(d[0]), "+f"(d[1]), "+f"(d[2]), "+f"(d[3])
        : "r"(a[0]), "r"(a[1]), "r"(a[2]), "r"(a[3]), "r"(b0), "r"(b1));
}
// fp16 inputs, fp32 accumulate (single pass, used in attention)
__device__ __forceinline__ void mma_f16(float* d, const uint32_t* a,
                                        uint32_t b0, uint32_t b1) {
    asm("mma.sync.aligned.m16n8k16.row.col.f32.f16.f16.f32 "
        "{%0,%1,%2,%3}, {%4,%5,%6,%7}, {%8,%9}, {%0,%1,%2,%3};"
        : "+f"(d[0]), "+f"(d[1]), "+f"(d[2]), "+f"(d[3])
        : "r"(a[0]), "r"(a[1]), "r"(a[2]), "r"(a[3]), "r"(b0), "r"(b1));
}
__device__ __forceinline__ uint32_t b2u(__nv_bfloat162 v) {
    return *reinterpret_cast<uint32_t*>(&v);
}
__device__ __forceinline__ uint32_t h2u(__half2 v) {
    return *reinterpret_cast<uint32_t*>(&v);
}
__device__ __forceinline__ void split_pair(float x, float y,
                                           uint32_t& hi, uint32_t& lo) {
    __nv_bfloat162 h = __float22bfloat162_rn(make_float2(x, y));
    float2 hf = __bfloat1622float2(h);
    __nv_bfloat162 l = __float22bfloat162_rn(make_float2(x - hf.x, y - hf.y));
    hi = b2u(h); lo = b2u(l);
}

// ---------------------------------------------------------------------------
// Conversion kernels
// ---------------------------------------------------------------------------
__global__ void split_kernel(const float* __restrict__ in,
                             __nv_bfloat16* __restrict__ hi,
                             __nv_bfloat16* __restrict__ lo, int n)
{
    int i = (blockIdx.x * blockDim.x + threadIdx.x) * 8;
    if (i >= n) return;
    float4 a = *(const float4*)(in + i);
    float4 b = *(const float4*)(in + i + 4);
    float v[8] = {a.x, a.y, a.z, a.w, b.x, b.y, b.z, b.w};
    __nv_bfloat16 h[8], l[8];
#pragma unroll
    for (int j = 0; j < 8; j++) {
        h[j] = __float2bfloat16(v[j]);
        l[j] = __float2bfloat16(v[j] - __bfloat162float(h[j]));
    }
    *(uint4*)(hi + i) = *(uint4*)h;
    *(uint4*)(lo + i) = *(uint4*)l;
}

// W [K][N] row-major -> Wt hi/lo [N][K]
__global__ void transpose_split(const float* __restrict__ W,
                                __nv_bfloat16* __restrict__ Thi,
                                __nv_bfloat16* __restrict__ Tlo,
                                int K, int N)
{
    __shared__ float tile[32][33];
    int k0 = blockIdx.y * 32, n0 = blockIdx.x * 32;
    int tx = threadIdx.x, ty = threadIdx.y;
#pragma unroll
    for (int i = ty; i < 32; i += 8)
        tile[i][tx] = W[(size_t)(k0 + i) * N + n0 + tx];
    __syncthreads();
#pragma unroll
    for (int i = ty; i < 32; i += 8) {
        float v = tile[tx][i];
        __nv_bfloat16 h = __float2bfloat16(v);
        float r = v - __bfloat162float(h);
        Thi[(size_t)(n0 + i) * K + k0 + tx] = h;
        Tlo[(size_t)(n0 + i) * K + k0 + tx] = __float2bfloat16(r);
    }
}

// ---------------------------------------------------------------------------
// mma.sync bf16 split GEMM — round-10 mainloop (496 us, 2 CTAs/SM).
// split_out=1: write fp16 qkv (single array) for the fp16 attention.
// split_out=0: write fp32 + bias to Co.
// ---------------------------------------------------------------------------
#define PAD 40
#define MAT_EL (128 * PAD)
#define MAT_B (MAT_EL * 2)
#define STAGE_B (4 * MAT_B)
#define GEMM_SMEM (2 * STAGE_B)
#define NCHUNK (GK / 32)

__global__ __launch_bounds__(256) void tc_gemm_mma(
    const __nv_bfloat16* __restrict__ Ah, const __nv_bfloat16* __restrict__ Al,
    const __nv_bfloat16* __restrict__ Bh, const __nv_bfloat16* __restrict__ Bl,
    const float* __restrict__ bias, float* __restrict__ Co,
    __half* __restrict__ Cf16, int N, int split_out)
{
    extern __shared__ char smem[];
    const uint32_t sb = smem_u32(smem);
    const int tid = threadIdx.x;
    const int wid = tid >> 5, lane = tid & 31;
    const int warp_m = wid >> 1, warp_n = wid & 1;
    const int m0 = blockIdx.y * 128, n0 = blockIdx.x * 128;

    const __nv_bfloat16* srcs[4] = {
        Ah + (size_t)m0 * GK, Al + (size_t)m0 * GK,
        Bh + (size_t)n0 * GK, Bl + (size_t)n0 * GK };

    auto prefetch = [&](int c, int stage) {
        const int k0 = c * 32;
        const uint32_t so = sb + stage * STAGE_B;
#pragma unroll
        for (int msel = 0; msel < 4; msel++) {
#pragma unroll
            for (int i = 0; i < 2; i++) {
                int idx = tid + i * 256;
                int r = idx >> 2, seg = idx & 3;
                uint32_t dst = so + msel * MAT_B + (uint32_t)(r * PAD + seg * 8) * 2;
                cp_async16(dst, srcs[msel] + (size_t)r * GK + k0 + seg * 8);
            }
        }
    };

    float acc[2][8][4];
#pragma unroll
    for (int a = 0; a < 2; a++)
#pragma unroll
        for (int b = 0; b < 8; b++)
#pragma unroll
            for (int c = 0; c < 4; c++) acc[a][b][c] = 0.f;

    prefetch(0, 0);
    cp_commit();

    const int a_row = (lane & 15);
    const int a_col8 = (lane >> 4) << 3;
    const int b_tile = lane >> 3;
    const int b_rin = lane & 7;
    const int b_nrow = ((b_tile >> 1) << 3) + b_rin;
    const int b_kcol = (b_tile & 1) << 3;

    for (int c = 0; c < NCHUNK; c++) {
        const int stage = c & 1;
        if (c + 1 < NCHUNK) { prefetch(c + 1, stage ^ 1); cp_commit(); }
        if (c + 1 < NCHUNK) cp_wait<1>(); else cp_wait<0>();
        __syncthreads();

        const uint32_t so = sb + stage * STAGE_B;
#pragma unroll
        for (int ks = 0; ks < 2; ks++) {
            uint32_t aH[2][4], aL[2][4];
#pragma unroll
            for (int mi = 0; mi < 2; mi++) {
                uint32_t off = (uint32_t)((warp_m * 32 + mi * 16 + a_row) * PAD
                                          + ks * 16 + a_col8) * 2;
                ldm_x4(aH[mi], so + 0 * MAT_B + off);
                ldm_x4(aL[mi], so + 1 * MAT_B + off);
            }
#pragma unroll
            for (int nj = 0; nj < 4; nj++) {
                uint32_t bH[4], bL[4];
                uint32_t off = (uint32_t)((warp_n * 64 + nj * 16 + b_nrow) * PAD
                                          + ks * 16 + b_kcol) * 2;
                ldm_x4(bH, so + 2 * MAT_B + off);
                ldm_x4(bL, so + 3 * MAT_B + off);
#pragma unroll
                for (int mi = 0; mi < 2; mi++) {
                    mma_bf16_v(acc[mi][nj * 2],     aH[mi], bH[0], bH[1]);
                    mma_bf16_v(acc[mi][nj * 2 + 1], aH[mi], bH[2], bH[3]);
                    mma_bf16_v(acc[mi][nj * 2],     aH[mi], bL[0], bL[1]);
                    mma_bf16_v(acc[mi][nj * 2 + 1], aH[mi], bL[2], bL[3]);
                    mma_bf16_v(acc[mi][nj * 2],     aL[mi], bH[0], bH[1]);
                    mma_bf16_v(acc[mi][nj * 2 + 1], aL[mi], bH[2], bH[3]);
                }
            }
        }
        __syncthreads();
    }

    const int r_base = m0 + warp_m * 32 + (lane >> 2);
    const int c_base = n0 + warp_n * 64 + (lane & 3) * 2;
    if (split_out) {
#pragma unroll
        for (int mi = 0; mi < 2; mi++) {
#pragma unroll
            for (int nj8 = 0; nj8 < 8; nj8++) {
                int col = c_base + nj8 * 8;
                float b0 = __ldg(bias + col), b1 = __ldg(bias + col + 1);
                int r0 = r_base + mi * 16;
                __half2 p0 = __float22half2_rn(
                    make_float2(acc[mi][nj8][0] + b0, acc[mi][nj8][1] + b1));
                __half2 p1 = __float22half2_rn(
                    make_float2(acc[mi][nj8][2] + b0, acc[mi][nj8][3] + b1));
                *(uint32_t*)(Cf16 + (size_t)r0 * N + col)       = h2u(p0);
                *(uint32_t*)(Cf16 + (size_t)(r0 + 8) * N + col) = h2u(p1);
            }
        }
    } else {
#pragma unroll
        for (int mi = 0; mi < 2; mi++) {
#pragma unroll
            for (int nj8 = 0; nj8 < 8; nj8++) {
                int col = c_base + nj8 * 8;
                float b0 = __ldg(bias + col), b1 = __ldg(bias + col + 1);
                int r0 = r_base + mi * 16;
                Co[(size_t)r0 * N + col]           = acc[mi][nj8][0] + b0;
                Co[(size_t)r0 * N + col + 1]       = acc[mi][nj8][1] + b1;
                Co[(size_t)(r0 + 8) * N + col]     = acc[mi][nj8][2] + b0;
                Co[(size_t)(r0 + 8) * N + col + 1] = acc[mi][nj8][3] + b1;
            }
        }
    }
}

// ---------------------------------------------------------------------------
// Tensor-core causal flash attention — SINGLE-PASS fp16 MMAs (round-10 loop
// structure; qkv is fp16 from the GEMM epilogue). Output y still written as
// bf16 hi/lo for the exact 3-pass proj GEMM.
// smem: Q[128][72] fp16 @0 (18432), 2 KV stages of {K,V}[64][72] (9216 each).
// ---------------------------------------------------------------------------
#define PADA 72
#define KTB  9216
#define QB   18432
#define KVS  (2 * KTB)                  // 18432 per stage
#define KVBASE QB
#define FLASH_SMEM (QB + 2 * KVS)       // 55296

__global__ __launch_bounds__(256) void flash_mma_kernel(
    const __half* __restrict__ qkvf,
    __nv_bfloat16* __restrict__ yhi, __nv_bfloat16* __restrict__ ylo)
{
    extern __shared__ __align__(16) char smem[];
    const uint32_t sb = smem_u32(smem);
    const int tid = threadIdx.x;
    const int wid = tid >> 5, lane = tid & 31;
    const int bh = blockIdx.x, b = bh >> 4, h = bh & 15;
    const int qt = (T_ / 128 - 1) - blockIdx.y;  // long CTAs first
    const int q0 = qt * 128;
    const size_t rowbase = (size_t)b * T_ * C3;

    auto fillKV = [&](int kt, int s) {
        const int k0 = kt * 64;
        const uint32_t so = sb + KVBASE + s * KVS;
#pragma unroll
        for (int i = 0; i < 4; i++) {
            int idx = tid + i * 256;       // 0..1023
            int mat = idx >> 9;            // 0=K 1=V
            int rem = idx & 511;
            int r = rem >> 3, seg = rem & 7;
            const __half* src = qkvf + rowbase + (size_t)(k0 + r) * C3
                                + (mat ? 2 * C_ : C_) + h * D_ + seg * 8;
            cp_async16(so + (uint32_t)(mat * KTB + r * 144 + seg * 16), src);
        }
    };

    // ---- stage Q (fp16; 1/8 applied to scores post-MMA) ----
    {
#pragma unroll
        for (int i = 0; i < 4; i++) {
            int idx = tid + i * 256;       // 0..1023
            int r = idx >> 3, seg = idx & 7;
            const __half* src = qkvf + rowbase + (size_t)(q0 + r) * C3
                                + h * D_ + seg * 8;
            cp_async16(sb + (uint32_t)(r * 144 + seg * 16), src);
        }
    }
    cp_commit();
    fillKV(0, 0);
    cp_commit();

    const int a_row = lane & 15;
    const int a_col8 = (lane >> 4) << 3;
    const int b_tile = lane >> 3;
    const int b_nrow = ((b_tile >> 1) << 3) + (lane & 7);
    const int b_kcol = (b_tile & 1) << 3;
    const int v_krow = ((b_tile & 1) << 3) + (lane & 7);
    const int v_ncol = (b_tile >> 1) << 3;

    cp_wait<1>();      // Q group done (KV0 may still be in flight)
    __syncthreads();

    uint32_t aQ[4][4];
#pragma unroll
    for (int ks = 0; ks < 4; ks++) {
        uint32_t off = (uint32_t)((wid * 16 + a_row) * PADA + ks * 16 + a_col8) * 2;
        ldm_x4(aQ[ks], sb + off);
    }

    float oacc[8][4];
#pragma unroll
    for (int i = 0; i < 8; i++)
#pragma unroll
        for (int j = 0; j < 4; j++) oacc[i][j] = 0.f;
    float mrow[2] = {-1e30f, -1e30f};
    float lrow[2] = {0.f, 0.f};

    const int ntiles = 2 * (qt + 1);
    for (int kt = 0; kt < ntiles; kt++) {
        const int s = kt & 1;
        const int k0 = kt * 64;
        __syncthreads();   // all warps done reading stage s^1 (tile kt-1)
        if (kt + 1 < ntiles) { fillKV(kt + 1, s ^ 1); cp_commit(); }
        if (kt + 1 < ntiles) cp_wait<1>(); else cp_wait<0>();
        __syncthreads();   // stage s (tile kt) visible to all

        const uint32_t kvso = sb + KVBASE + s * KVS;

        // ---- S = Q @ K^T (single-pass fp16) ----
        float sacc[8][4];
#pragma unroll
        for (int i = 0; i < 8; i++)
#pragma unroll
            for (int j = 0; j < 4; j++) sacc[i][j] = 0.f;
#pragma unroll
        for (int ks = 0; ks < 4; ks++) {
            uint32_t bK[4];
#pragma unroll
            for (int nj = 0; nj < 4; nj++) {
                uint32_t off = (uint32_t)((nj * 16 + b_nrow) * PADA
                                          + ks * 16 + b_kcol) * 2;
                ldm_x4(bK, kvso + off);
                mma_f16(sacc[nj * 2],     aQ[ks], bK[0], bK[1]);
                mma_f16(sacc[nj * 2 + 1], aQ[ks], bK[2], bK[3]);
            }
        }
        // apply 1/sqrt(D) = 1/8 (exact pow2)
#pragma unroll
        for (int nb = 0; nb < 8; nb++) {
            sacc[nb][0] *= 0.125f; sacc[nb][1] *= 0.125f;
            sacc[nb][2] *= 0.125f; sacc[nb][3] *= 0.125f;
        }

        // ---- causal mask (last two tiles only) ----
        if (k0 >= q0) {
            const int qg = q0 + wid * 16 + (lane >> 2);
            const int cg = k0 + (lane & 3) * 2;
#pragma unroll
            for (int nb = 0; nb < 8; nb++) {
                int col = cg + nb * 8;
                if (col > qg)          sacc[nb][0] = -1e30f;
                if (col + 1 > qg)      sacc[nb][1] = -1e30f;
                if (col > qg + 8)      sacc[nb][2] = -1e30f;
                if (col + 1 > qg + 8)  sacc[nb][3] = -1e30f;
            }
        }

        // ---- online softmax ----
        float mn0 = mrow[0], mn1 = mrow[1];
#pragma unroll
        for (int nb = 0; nb < 8; nb++) {
            mn0 = fmaxf(mn0, fmaxf(sacc[nb][0], sacc[nb][1]));
            mn1 = fmaxf(mn1, fmaxf(sacc[nb][2], sacc[nb][3]));
        }
        mn0 = fmaxf(mn0, __shfl_xor_sync(0xFFFFFFFF, mn0, 1));
        mn0 = fmaxf(mn0, __shfl_xor_sync(0xFFFFFFFF, mn0, 2));
        mn1 = fmaxf(mn1, __shfl_xor_sync(0xFFFFFFFF, mn1, 1));
        mn1 = fmaxf(mn1, __shfl_xor_sync(0xFFFFFFFF, mn1, 2));
        const float corr0 = __expf(mrow[0] - mn0);
        const float corr1 = __expf(mrow[1] - mn1);
        mrow[0] = mn0; mrow[1] = mn1;

        float ps0 = 0.f, ps1 = 0.f;
#pragma unroll
        for (int nb = 0; nb < 8; nb++) {
            sacc[nb][0] = __expf(sacc[nb][0] - mn0);
            sacc[nb][1] = __expf(sacc[nb][1] - mn0);
            sacc[nb][2] = __expf(sacc[nb][2] - mn1);
            sacc[nb][3] = __expf(sacc[nb][3] - mn1);
            ps0 += sacc[nb][0] + sacc[nb][1];
            ps1 += sacc[nb][2] + sacc[nb][3];
        }
        ps0 += __shfl_xor_sync(0xFFFFFFFF, ps0, 1);
        ps0 += __shfl_xor_sync(0xFFFFFFFF, ps0, 2);
        ps1 += __shfl_xor_sync(0xFFFFFFFF, ps1, 1);
        ps1 += __shfl_xor_sync(0xFFFFFFFF, ps1, 2);
        lrow[0] = lrow[0] * corr0 + ps0;
        lrow[1] = lrow[1] * corr1 + ps1;
#pragma unroll
        for (int nb = 0; nb < 8; nb++) {
            oacc[nb][0] *= corr0; oacc[nb][1] *= corr0;
            oacc[nb][2] *= corr1; oacc[nb][3] *= corr1;
        }

        // ---- O += P @ V (single-pass fp16, V via ldmatrix.trans) ----
#pragma unroll
        for (int ks = 0; ks < 4; ks++) {
            uint32_t pF[4];
            pF[0] = h2u(__float22half2_rn(
                make_float2(sacc[2 * ks][0], sacc[2 * ks][1])));
            pF[1] = h2u(__float22half2_rn(
                make_float2(sacc[2 * ks][2], sacc[2 * ks][3])));
            pF[2] = h2u(__float22half2_rn(
                make_float2(sacc[2 * ks + 1][0], sacc[2 * ks + 1][1])));
            pF[3] = h2u(__float22half2_rn(
                make_float2(sacc[2 * ks + 1][2], sacc[2 * ks + 1][3])));
#pragma unroll
            for (int nj = 0; nj < 4; nj++) {
                uint32_t bV[4];
                uint32_t off = (uint32_t)((ks * 16 + v_krow) * PADA
                                          + nj * 16 + v_ncol) * 2;
                ldm_x4_trans(bV, kvso + KTB + off);
                mma_f16(oacc[nj * 2],     pF, bV[0], bV[1]);
                mma_f16(oacc[nj * 2 + 1], pF, bV[2], bV[3]);
            }
        }
    }

    // ---- normalize and write y as bf16 hi/lo (fused split for proj) ----
    const float inv0 = 1.f / lrow[0];
    const float inv1 = 1.f / lrow[1];
    const int rg = q0 + wid * 16 + (lane >> 2);
    const size_t e0 = ((size_t)b * T_ + rg) * C_ + h * D_ + (lane & 3) * 2;
#pragma unroll
    for (int nb = 0; nb < 8; nb++) {
        uint32_t h0, l0, h1, l1;
        split_pair(oacc[nb][0] * inv0, oacc[nb][1] * inv0, h0, l0);
        split_pair(oacc[nb][2] * inv1, oacc[nb][3] * inv1, h1, l1);
        *(uint32_t*)(yhi + e0 + nb * 8)          = h0;
        *(uint32_t*)(ylo + e0 + nb * 8)          = l0;
        *(uint32_t*)(yhi + e0 + 8 * C_ + nb * 8) = h1;
        *(uint32_t*)(ylo + e0 + 8 * C_ + nb * 8) = l1;
    }
}

// ---------------------------------------------------------------------------
extern "C" void kernel_launch(void* const* d_in, const int* in_sizes, int n_in,
                              void* d_out, int out_size)
{
    const float* x      = (const float*)d_in[0];
    const float* W_attn = (const float*)d_in[1];
    const float* b_attn = (const float*)d_in[2];
    const float* W_proj = (const float*)d_in[3];
    const float* b_proj = (const float*)d_in[4];
    float* out = (float*)d_out;

    __half* qkvf;
    __nv_bfloat16 *xhi, *xlo, *yhi, *ylo, *wahi, *walo, *wphi, *wplo;
    cudaGetSymbolAddress((void**)&qkvf, g_qkvf);
    cudaGetSymbolAddress((void**)&xhi, g_xhi);
    cudaGetSymbolAddress((void**)&xlo, g_xlo);
    cudaGetSymbolAddress((void**)&yhi, g_yhi);
    cudaGetSymbolAddress((void**)&ylo, g_ylo);
    cudaGetSymbolAddress((void**)&wahi, g_wahi);
    cudaGetSymbolAddress((void**)&walo, g_walo);
    cudaGetSymbolAddress((void**)&wphi, g_wphi);
    cudaGetSymbolAddress((void**)&wplo, g_wplo);

    cudaFuncSetAttribute(tc_gemm_mma, cudaFuncAttributeMaxDynamicSharedMemorySize,
                         GEMM_SMEM);
    cudaFuncSetAttribute(flash_mma_kernel,
                         cudaFuncAttributeMaxDynamicSharedMemorySize, FLASH_SMEM);

    const int NTOK_EL = M_TOK * C_;

    // 1) split x -> bf16 hi/lo
    split_kernel<<<NTOK_EL / 8 / 256, 256>>>(x, xhi, xlo, NTOK_EL);
    // 2) transpose+split weights
    transpose_split<<<dim3(C3 / 32, C_ / 32), dim3(32, 8)>>>(W_attn, wahi, walo, C_, C3);
    transpose_split<<<dim3(C_ / 32, C_ / 32), dim3(32, 8)>>>(W_proj, wphi, wplo, C_, C_);
    // 3) QKV GEMM (exact 3-pass bf16) -> qkv fp16
    tc_gemm_mma<<<dim3(C3 / 128, M_TOK / 128), 256, GEMM_SMEM>>>(
        xhi, xlo, wahi, walo, b_attn, nullptr, qkvf, C3, 1);
    // 4) causal flash attention (single-pass fp16 tensor cores)
    flash_mma_kernel<<<dim3(B_ * H_, T_ / 128), 256, FLASH_SMEM>>>(
        qkvf, yhi, ylo);
    // 5) proj GEMM (exact 3-pass bf16) -> d_out
    tc_gemm_mma<<<dim3(C_ / 128, M_TOK / 128), 256, GEMM_SMEM>>>(
        yhi, ylo, wphi, wplo, b_proj, out, nullptr, C_, 0);
}

// round 14
// speedup vs baseline: 1.8010x; 1.2595x over previous
#include <cuda_runtime.h>
#include <cuda_bf16.h>
#include <cuda_fp16.h>
#include <cstdint>
#include <cstddef>

// Problem constants
#define B_  4
#define T_  2048
#define C_  1024
#define H_  16
#define D_  64
#define M_TOK (B_ * T_)      // 8192
#define C3 (3 * C_)          // 3072
#define GK 1024              // K of both GEMMs

// ---------------------------------------------------------------------------
// Scratch (device globals; allocation in kernel_launch is forbidden)
// ---------------------------------------------------------------------------
__device__ __half g_qkvf[(size_t)M_TOK * C3];   // qkv fp16 (from GEMM epi)
__device__ __half g_xf[(size_t)M_TOK * C_];     // x fp16
__device__ __half g_yf[(size_t)M_TOK * C_];     // attention out fp16
__device__ __half g_wah[(size_t)C3 * C_];       // W_attn^T hi fp16 [3C][C]
__device__ __half g_wal[(size_t)C3 * C_];       // W_attn^T lo fp16
__device__ __half g_wph[(size_t)C_ * C_];       // W_proj^T hi fp16 [C][C]
__device__ __half g_wpl[(size_t)C_ * C_];       // W_proj^T lo fp16

// ---------------------------------------------------------------------------
// PTX helpers
// ---------------------------------------------------------------------------
__device__ __forceinline__ uint32_t smem_u32(const void* p) {
    uint32_t a;
    asm("{ .reg .u64 t; cvta.to.shared.u64 t, %1; cvt.u32.u64 %0, t; }"
        : "=r"(a) : "l"(p));
    return a;
}
__device__ __forceinline__ void cp_async16(uint32_t dst, const void* src) {
    asm volatile("cp.async.cg.shared.global [%0], [%1], 16;"
                 :: "r"(dst), "l"(src) : "memory");
}
__device__ __forceinline__ void cp_commit() {
    asm volatile("cp.async.commit_group;" ::: "memory");
}
template <int N>
__device__ __forceinline__ void cp_wait() {
    asm volatile("cp.async.wait_group %0;" :: "n"(N) : "memory");
}
__device__ __forceinline__ void ldm_x4(uint32_t* r, uint32_t addr) {
    asm volatile("ldmatrix.sync.aligned.m8n8.x4.shared.b16 {%0,%1,%2,%3}, [%4];"
                 : "=r"(r[0]), "=r"(r[1]), "=r"(r[2]), "=r"(r[3]) : "r"(addr));
}
__device__ __forceinline__ void ldm_x4_trans(uint32_t* r, uint32_t addr) {
    asm volatile("ldmatrix.sync.aligned.m8n8.x4.trans.shared.b16 {%0,%1,%2,%3}, [%4];"
                 : "=r"(r[0]), "=r"(r[1]), "=r"(r[2]), "=r"(r[3]) : "r"(addr));
}
// fp16 mma, volatile (GEMM — keeps R10 register allocation behavior)
__device__ __forceinline__ void mma_f16_v(float* d, const uint32_t* a,
                                          uint32_t b0, uint32_t b1) {
    asm volatile(
        "mma.sync.aligned.m16n8k16.row.col.f32.f16.f16.f32 "
        "{%0,%1,%2,%3}, {%4,%5,%6,%7}, {%8,%9}, {%0,%1,%2,%3};"
        : "+f"(d[0]), "+f"(d[1]), "+f"(d[2]), "+f"(d[3])
        : "r"(a[0]), "r"(a[1]), "r"(a[2]), "r"(a[3]), "r"(b0), "r"(b1));
}
// fp16 mma, non-volatile (attention)
__device__ __forceinline__ void mma_f16(float* d, const uint32_t* a,
                                        uint32_t b0, uint32_t b1) {
    asm("mma.sync.aligned.m16n8k16.row.col.f32.f16.f16.f32 "
        "{%0,%1,%2,%3}, {%4,%5,%6,%7}, {%8,%9}, {%0,%1,%2,%3};"
        : "+f"(d[0]), "+f"(d[1]), "+f"(d[2]), "+f"(d[3])
        : "r"(a[0]), "r"(a[1]), "r"(a[2]), "r"(a[3]), "r"(b0), "r"(b1));
}
__device__ __forceinline__ uint32_t h2u(__half2 v) {
    return *reinterpret_cast<uint32_t*>(&v);
}

// ---------------------------------------------------------------------------
// Conversion kernels
// ---------------------------------------------------------------------------
__global__ void cvt_f16_kernel(const float* __restrict__ in,
                               __half* __restrict__ out, int n)
{
    int i = (blockIdx.x * blockDim.x + threadIdx.x) * 8;
    if (i >= n) return;
    float4 a = *(const float4*)(in + i);
    float4 b = *(const float4*)(in + i + 4);
    __half h[8];
    h[0] = __float2half_rn(a.x); h[1] = __float2half_rn(a.y);
    h[2] = __float2half_rn(a.z); h[3] = __float2half_rn(a.w);
    h[4] = __float2half_rn(b.x); h[5] = __float2half_rn(b.y);
    h[6] = __float2half_rn(b.z); h[7] = __float2half_rn(b.w);
    *(uint4*)(out + i) = *(uint4*)h;
}

// W [K][N] row-major -> Wt hi/lo fp16 [N][K] (hi+lo represents W to ~2^-24)
__global__ void transpose_split_f16(const float* __restrict__ W,
                                    __half* __restrict__ Thi,
                                    __half* __restrict__ Tlo,
                                    int K, int N)
{
    __shared__ float tile[32][33];
    int k0 = blockIdx.y * 32, n0 = blockIdx.x * 32;
    int tx = threadIdx.x, ty = threadIdx.y;
#pragma unroll
    for (int i = ty; i < 32; i += 8)
        tile[i][tx] = W[(size_t)(k0 + i) * N + n0 + tx];
    __syncthreads();
#pragma unroll
    for (int i = ty; i < 32; i += 8) {
        float v = tile[tx][i];
        __half h = __float2half_rn(v);
        float r = v - __half2float(h);
        Thi[(size_t)(n0 + i) * K + k0 + tx] = h;
        Tlo[(size_t)(n0 + i) * K + k0 + tx] = __float2half_rn(r);
    }
}

// ---------------------------------------------------------------------------
// mma.sync fp16 2-pass GEMM: C = A @ (Wh + Wl)^T + bias.
// A single fp16 (quantized input), W split fp16 hi/lo (near-exact).
// Same 128x128 / BK=32 / 8-warp / 2-CTA-per-SM geometry as round 10.
// split_out=1: write fp16 (qkv); split_out=0: write fp32 (final output).
// ---------------------------------------------------------------------------
#define PAD 40
#define MAT_B (128 * PAD * 2)           // 10240
#define STAGE_B (3 * MAT_B)             // 30720 (A, Bh, Bl)
#define GEMM_SMEM (2 * STAGE_B)         // 61440
#define NCHUNK (GK / 32)

__global__ __launch_bounds__(256) void tc_gemm_mma(
    const __half* __restrict__ Af,
    const __half* __restrict__ Bh, const __half* __restrict__ Bl,
    const float* __restrict__ bias, float* __restrict__ Co,
    __half* __restrict__ Cf16, int N, int split_out)
{
    extern __shared__ char smem[];
    const uint32_t sb = smem_u32(smem);
    const int tid = threadIdx.x;
    const int wid = tid >> 5, lane = tid & 31;
    const int warp_m = wid >> 1, warp_n = wid & 1;
    const int m0 = blockIdx.y * 128, n0 = blockIdx.x * 128;

    const __half* srcs[3] = {
        Af + (size_t)m0 * GK, Bh + (size_t)n0 * GK, Bl + (size_t)n0 * GK };

    // 1536 16B segments per stage (3 matrices x 512), 6 per thread
    auto prefetch = [&](int c, int stage) {
        const int k0 = c * 32;
        const uint32_t so = sb + stage * STAGE_B;
#pragma unroll
        for (int msel = 0; msel < 3; msel++) {
#pragma unroll
            for (int i = 0; i < 2; i++) {
                int idx = tid + i * 256;
                int r = idx >> 2, seg = idx & 3;
                uint32_t dst = so + msel * MAT_B + (uint32_t)(r * PAD + seg * 8) * 2;
                cp_async16(dst, srcs[msel] + (size_t)r * GK + k0 + seg * 8);
            }
        }
    };

    float acc[2][8][4];
#pragma unroll
    for (int a = 0; a < 2; a++)
#pragma unroll
        for (int b = 0; b < 8; b++)
#pragma unroll
            for (int c = 0; c < 4; c++) acc[a][b][c] = 0.f;

    prefetch(0, 0);
    cp_commit();

    const int a_row = (lane & 15);
    const int a_col8 = (lane >> 4) << 3;
    const int b_tile = lane >> 3;
    const int b_rin = lane & 7;
    const int b_nrow = ((b_tile >> 1) << 3) + b_rin;
    const int b_kcol = (b_tile & 1) << 3;

    for (int c = 0; c < NCHUNK; c++) {
        const int stage = c & 1;
        if (c + 1 < NCHUNK) { prefetch(c + 1, stage ^ 1); cp_commit(); }
        if (c + 1 < NCHUNK) cp_wait<1>(); else cp_wait<0>();
        __syncthreads();

        const uint32_t so = sb + stage * STAGE_B;
#pragma unroll
        for (int ks = 0; ks < 2; ks++) {
            uint32_t aF[2][4];
#pragma unroll
            for (int mi = 0; mi < 2; mi++) {
                uint32_t off = (uint32_t)((warp_m * 32 + mi * 16 + a_row) * PAD
                                          + ks * 16 + a_col8) * 2;
                ldm_x4(aF[mi], so + off);
            }
#pragma unroll
            for (int nj = 0; nj < 4; nj++) {
                uint32_t bH[4], bL[4];
                uint32_t off = (uint32_t)((warp_n * 64 + nj * 16 + b_nrow) * PAD
                                          + ks * 16 + b_kcol) * 2;
                ldm_x4(bH, so + 1 * MAT_B + off);
                ldm_x4(bL, so + 2 * MAT_B + off);
#pragma unroll
                for (int mi = 0; mi < 2; mi++) {
                    mma_f16_v(acc[mi][nj * 2],     aF[mi], bH[0], bH[1]);
                    mma_f16_v(acc[mi][nj * 2 + 1], aF[mi], bH[2], bH[3]);
                    mma_f16_v(acc[mi][nj * 2],     aF[mi], bL[0], bL[1]);
                    mma_f16_v(acc[mi][nj * 2 + 1], aF[mi], bL[2], bL[3]);
                }
            }
        }
        __syncthreads();
    }

    const int r_base = m0 + warp_m * 32 + (lane >> 2);
    const int c_base = n0 + warp_n * 64 + (lane & 3) * 2;
    if (split_out) {
#pragma unroll
        for (int mi = 0; mi < 2; mi++) {
#pragma unroll
            for (int nj8 = 0; nj8 < 8; nj8++) {
                int col = c_base + nj8 * 8;
                float b0 = __ldg(bias + col), b1 = __ldg(bias + col + 1);
                int r0 = r_base + mi * 16;
                __half2 p0 = __float22half2_rn(
                    make_float2(acc[mi][nj8][0] + b0, acc[mi][nj8][1] + b1));
                __half2 p1 = __float22half2_rn(
                    make_float2(acc[mi][nj8][2] + b0, acc[mi][nj8][3] + b1));
                *(uint32_t*)(Cf16 + (size_t)r0 * N + col)       = h2u(p0);
                *(uint32_t*)(Cf16 + (size_t)(r0 + 8) * N + col) = h2u(p1);
            }
        }
    } else {
#pragma unroll
        for (int mi = 0; mi < 2; mi++) {
#pragma unroll
            for (int nj8 = 0; nj8 < 8; nj8++) {
                int col = c_base + nj8 * 8;
                float b0 = __ldg(bias + col), b1 = __ldg(bias + col + 1);
                int r0 = r_base + mi * 16;
                Co[(size_t)r0 * N + col]           = acc[mi][nj8][0] + b0;
                Co[(size_t)r0 * N + col + 1]       = acc[mi][nj8][1] + b1;
                Co[(size_t)(r0 + 8) * N + col]     = acc[mi][nj8][2] + b0;
                Co[(size_t)(r0 + 8) * N + col + 1] = acc[mi][nj8][3] + b1;
            }
        }
    }
}

// ---------------------------------------------------------------------------
// Tensor-core causal flash attention — single-pass fp16 (round-13, proven).
// Output y now written as single fp16 for the 2-pass proj GEMM.
// ---------------------------------------------------------------------------
#define PADA 72
#define KTB  9216
#define QB   18432
#define KVS  (2 * KTB)
#define KVBASE QB
#define FLASH_SMEM (QB + 2 * KVS)       // 55296

__global__ __launch_bounds__(256) void flash_mma_kernel(
    const __half* __restrict__ qkvf, __half* __restrict__ yf)
{
    extern __shared__ __align__(16) char smem[];
    const uint32_t sb = smem_u32(smem);
    const int tid = threadIdx.x;
    const int wid = tid >> 5, lane = tid & 31;
    const int bh = blockIdx.x, b = bh >> 4, h = bh & 15;
    const int qt = (T_ / 128 - 1) - blockIdx.y;  // long CTAs first
    const int q0 = qt * 128;
    const size_t rowbase = (size_t)b * T_ * C3;

    auto fillKV = [&](int kt, int s) {
        const int k0 = kt * 64;
        const uint32_t so = sb + KVBASE + s * KVS;
#pragma unroll
        for (int i = 0; i < 4; i++) {
            int idx = tid + i * 256;
            int mat = idx >> 9;            // 0=K 1=V
            int rem = idx & 511;
            int r = rem >> 3, seg = rem & 7;
            const __half* src = qkvf + rowbase + (size_t)(k0 + r) * C3
                                + (mat ? 2 * C_ : C_) + h * D_ + seg * 8;
            cp_async16(so + (uint32_t)(mat * KTB + r * 144 + seg * 16), src);
        }
    };

    // ---- stage Q ----
    {
#pragma unroll
        for (int i = 0; i < 4; i++) {
            int idx = tid + i * 256;
            int r = idx >> 3, seg = idx & 7;
            const __half* src = qkvf + rowbase + (size_t)(q0 + r) * C3
                                + h * D_ + seg * 8;
            cp_async16(sb + (uint32_t)(r * 144 + seg * 16), src);
        }
    }
    cp_commit();
    fillKV(0, 0);
    cp_commit();

    const int a_row = lane & 15;
    const int a_col8 = (lane >> 4) << 3;
    const int b_tile = lane >> 3;
    const int b_nrow = ((b_tile >> 1) << 3) + (lane & 7);
    const int b_kcol = (b_tile & 1) << 3;
    const int v_krow = ((b_tile & 1) << 3) + (lane & 7);
    const int v_ncol = (b_tile >> 1) << 3;

    cp_wait<1>();
    __syncthreads();

    uint32_t aQ[4][4];
#pragma unroll
    for (int ks = 0; ks < 4; ks++) {
        uint32_t off = (uint32_t)((wid * 16 + a_row) * PADA + ks * 16 + a_col8) * 2;
        ldm_x4(aQ[ks], sb + off);
    }

    float oacc[8][4];
#pragma unroll
    for (int i = 0; i < 8; i++)
#pragma unroll
        for (int j = 0; j < 4; j++) oacc[i][j] = 0.f;
    float mrow[2] = {-1e30f, -1e30f};
    float lrow[2] = {0.f, 0.f};

    const int ntiles = 2 * (qt + 1);
    for (int kt = 0; kt < ntiles; kt++) {
        const int s = kt & 1;
        const int k0 = kt * 64;
        __syncthreads();
        if (kt + 1 < ntiles) { fillKV(kt + 1, s ^ 1); cp_commit(); }
        if (kt + 1 < ntiles) cp_wait<1>(); else cp_wait<0>();
        __syncthreads();

        const uint32_t kvso = sb + KVBASE + s * KVS;

        // ---- S = Q @ K^T ----
        float sacc[8][4];
#pragma unroll
        for (int i = 0; i < 8; i++)
#pragma unroll
            for (int j = 0; j < 4; j++) sacc[i][j] = 0.f;
#pragma unroll
        for (int ks = 0; ks < 4; ks++) {
            uint32_t bK[4];
#pragma unroll
            for (int nj = 0; nj < 4; nj++) {
                uint32_t off = (uint32_t)((nj * 16 + b_nrow) * PADA
                                          + ks * 16 + b_kcol) * 2;
                ldm_x4(bK, kvso + off);
                mma_f16(sacc[nj * 2],     aQ[ks], bK[0], bK[1]);
                mma_f16(sacc[nj * 2 + 1], aQ[ks], bK[2], bK[3]);
            }
        }
#pragma unroll
        for (int nb = 0; nb < 8; nb++) {
            sacc[nb][0] *= 0.125f; sacc[nb][1] *= 0.125f;
            sacc[nb][2] *= 0.125f; sacc[nb][3] *= 0.125f;
        }

        // ---- causal mask (last two tiles only) ----
        if (k0 >= q0) {
            const int qg = q0 + wid * 16 + (lane >> 2);
            const int cg = k0 + (lane & 3) * 2;
#pragma unroll
            for (int nb = 0; nb < 8; nb++) {
                int col = cg + nb * 8;
                if (col > qg)          sacc[nb][0] = -1e30f;
                if (col + 1 > qg)      sacc[nb][1] = -1e30f;
                if (col > qg + 8)      sacc[nb][2] = -1e30f;
                if (col + 1 > qg + 8)  sacc[nb][3] = -1e30f;
            }
        }

        // ---- online softmax ----
        float mn0 = mrow[0], mn1 = mrow[1];
#pragma unroll
        for (int nb = 0; nb < 8; nb++) {
            mn0 = fmaxf(mn0, fmaxf(sacc[nb][0], sacc[nb][1]));
            mn1 = fmaxf(mn1, fmaxf(sacc[nb][2], sacc[nb][3]));
        }
        mn0 = fmaxf(mn0, __shfl_xor_sync(0xFFFFFFFF, mn0, 1));
        mn0 = fmaxf(mn0, __shfl_xor_sync(0xFFFFFFFF, mn0, 2));
        mn1 = fmaxf(mn1, __shfl_xor_sync(0xFFFFFFFF, mn1, 1));
        mn1 = fmaxf(mn1, __shfl_xor_sync(0xFFFFFFFF, mn1, 2));
        const float corr0 = __expf(mrow[0] - mn0);
        const float corr1 = __expf(mrow[1] - mn1);
        mrow[0] = mn0; mrow[1] = mn1;

        float ps0 = 0.f, ps1 = 0.f;
#pragma unroll
        for (int nb = 0; nb < 8; nb++) {
            sacc[nb][0] = __expf(sacc[nb][0] - mn0);
            sacc[nb][1] = __expf(sacc[nb][1] - mn0);
            sacc[nb][2] = __expf(sacc[nb][2] - mn1);
            sacc[nb][3] = __expf(sacc[nb][3] - mn1);
            ps0 += sacc[nb][0] + sacc[nb][1];
            ps1 += sacc[nb][2] + sacc[nb][3];
        }
        ps0 += __shfl_xor_sync(0xFFFFFFFF, ps0, 1);
        ps0 += __shfl_xor_sync(0xFFFFFFFF, ps0, 2);
        ps1 += __shfl_xor_sync(0xFFFFFFFF, ps1, 1);
        ps1 += __shfl_xor_sync(0xFFFFFFFF, ps1, 2);
        lrow[0] = lrow[0] * corr0 + ps0;
        lrow[1] = lrow[1] * corr1 + ps1;
#pragma unroll
        for (int nb = 0; nb < 8; nb++) {
            oacc[nb][0] *= corr0; oacc[nb][1] *= corr0;
            oacc[nb][2] *= corr1; oacc[nb][3] *= corr1;
        }

        // ---- O += P @ V ----
#pragma unroll
        for (int ks = 0; ks < 4; ks++) {
            uint32_t pF[4];
            pF[0] = h2u(__float22half2_rn(
                make_float2(sacc[2 * ks][0], sacc[2 * ks][1])));
            pF[1] = h2u(__float22half2_rn(
                make_float2(sacc[2 * ks][2], sacc[2 * ks][3])));
            pF[2] = h2u(__float22half2_rn(
                make_float2(sacc[2 * ks + 1][0], sacc[2 * ks + 1][1])));
            pF[3] = h2u(__float22half2_rn(
                make_float2(sacc[2 * ks + 1][2], sacc[2 * ks + 1][3])));
#pragma unroll
            for (int nj = 0; nj < 4; nj++) {
                uint32_t bV[4];
                uint32_t off = (uint32_t)((ks * 16 + v_krow) * PADA
                                          + nj * 16 + v_ncol) * 2;
                ldm_x4_trans(bV, kvso + KTB + off);
                mma_f16(oacc[nj * 2],     pF, bV[0], bV[1]);
                mma_f16(oacc[nj * 2 + 1], pF, bV[2], bV[3]);
            }
        }
    }

    // ---- normalize and write y as single fp16 ----
    const float inv0 = 1.f / lrow[0];
    const float inv1 = 1.f / lrow[1];
    const int rg = q0 + wid * 16 + (lane >> 2);
    const size_t e0 = ((size_t)b * T_ + rg) * C_ + h * D_ + (lane & 3) * 2;
#pragma unroll
    for (int nb = 0; nb < 8; nb++) {
        __half2 o0 = __float22half2_rn(
            make_float2(oacc[nb][0] * inv0, oacc[nb][1] * inv0));
        __half2 o1 = __float22half2_rn(
            make_float2(oacc[nb][2] * inv1, oacc[nb][3] * inv1));
        *(uint32_t*)(yf + e0 + nb * 8)          = h2u(o0);
        *(uint32_t*)(yf + e0 + 8 * C_ + nb * 8) = h2u(o1);
    }
}

// ---------------------------------------------------------------------------
extern "C" void kernel_launch(void* const* d_in, const int* in_sizes, int n_in,
                              void* d_out, int out_size)
{
    const float* x      = (const float*)d_in[0];
    const float* W_attn = (const float*)d_in[1];
    const float* b_attn = (const float*)d_in[2];
    const float* W_proj = (const float*)d_in[3];
    const float* b_proj = (const float*)d_in[4];
    float* out = (float*)d_out;

    __half *qkvf, *xf, *yf, *wah, *wal, *wph, *wpl;
    cudaGetSymbolAddress((void**)&qkvf, g_qkvf);
    cudaGetSymbolAddress((void**)&xf, g_xf);
    cudaGetSymbolAddress((void**)&yf, g_yf);
    cudaGetSymbolAddress((void**)&wah, g_wah);
    cudaGetSymbolAddress((void**)&wal, g_wal);
    cudaGetSymbolAddress((void**)&wph, g_wph);
    cudaGetSymbolAddress((void**)&wpl, g_wpl);

    cudaFuncSetAttribute(tc_gemm_mma, cudaFuncAttributeMaxDynamicSharedMemorySize,
                         GEMM_SMEM);
    cudaFuncSetAttribute(flash_mma_kernel,
                         cudaFuncAttributeMaxDynamicSharedMemorySize, FLASH_SMEM);

    const int NTOK_EL = M_TOK * C_;

    // 1) x -> fp16
    cvt_f16_kernel<<<NTOK_EL / 8 / 256, 256>>>(x, xf, NTOK_EL);
    // 2) transpose+split weights -> fp16 hi/lo (near-exact W)
    transpose_split_f16<<<dim3(C3 / 32, C_ / 32), dim3(32, 8)>>>(W_attn, wah, wal, C_, C3);
    transpose_split_f16<<<dim3(C_ / 32, C_ / 32), dim3(32, 8)>>>(W_proj, wph, wpl, C_, C_);
    // 3) QKV GEMM (2-pass fp16) -> qkv fp16
    tc_gemm_mma<<<dim3(C3 / 128, M_TOK / 128), 256, GEMM_SMEM>>>(
        xf, wah, wal, b_attn, nullptr, qkvf, C3, 1);
    // 4) causal flash attention (single-pass fp16 tensor cores)
    flash_mma_kernel<<<dim3(B_ * H_, T_ / 128), 256, FLASH_SMEM>>>(qkvf, yf);
    // 5) proj GEMM (2-pass fp16) -> d_out fp32
    tc_gemm_mma<<<dim3(C_ / 128, M_TOK / 128), 256, GEMM_SMEM>>>(
        yf, wph, wpl, b_proj, out, nullptr, C_, 0);
}

// round 15
// speedup vs baseline: 2.5501x; 1.4159x over previous
#include <cuda_runtime.h>
#include <cuda_bf16.h>
#include <cuda_fp16.h>
#include <cstdint>
#include <cstddef>

// Problem constants
#define B_  4
#define T_  2048
#define C_  1024
#define H_  16
#define D_  64
#define M_TOK (B_ * T_)      // 8192
#define C3 (3 * C_)          // 3072
#define GK 1024              // K of both GEMMs

// ---------------------------------------------------------------------------
// Scratch (device globals; allocation in kernel_launch is forbidden)
// ---------------------------------------------------------------------------
__device__ __half g_qkvf[(size_t)M_TOK * C3];   // qkv fp16 (from GEMM epi)
__device__ __half g_xf[(size_t)M_TOK * C_];     // x fp16
__device__ __half g_yf[(size_t)M_TOK * C_];     // attention out fp16
__device__ __half g_waf[(size_t)C3 * C_];       // W_attn^T fp16 [3C][C]
__device__ __half g_wpf[(size_t)C_ * C_];       // W_proj^T fp16 [C][C]

// ---------------------------------------------------------------------------
// PTX helpers
// ---------------------------------------------------------------------------
__device__ __forceinline__ uint32_t smem_u32(const void* p) {
    uint32_t a;
    asm("{ .reg .u64 t; cvta.to.shared.u64 t, %1; cvt.u32.u64 %0, t; }"
        : "=r"(a) : "l"(p));
    return a;
}
__device__ __forceinline__ void cp_async16(uint32_t dst, const void* src) {
    asm volatile("cp.async.cg.shared.global [%0], [%1], 16;"
                 :: "r"(dst), "l"(src) : "memory");
}
__device__ __forceinline__ void cp_commit() {
    asm volatile("cp.async.commit_group;" ::: "memory");
}
template <int N>
__device__ __forceinline__ void cp_wait() {
    asm volatile("cp.async.wait_group %0;" :: "n"(N) : "memory");
}
__device__ __forceinline__ void ldm_x4(uint32_t* r, uint32_t addr) {
    asm volatile("ldmatrix.sync.aligned.m8n8.x4.shared.b16 {%0,%1,%2,%3}, [%4];"
                 : "=r"(r[0]), "=r"(r[1]), "=r"(r[2]), "=r"(r[3]) : "r"(addr));
}
__device__ __forceinline__ void ldm_x4_trans(uint32_t* r, uint32_t addr) {
    asm volatile("ldmatrix.sync.aligned.m8n8.x4.trans.shared.b16 {%0,%1,%2,%3}, [%4];"
                 : "=r"(r[0]), "=r"(r[1]), "=r"(r[2]), "=r"(r[3]) : "r"(addr));
}
// fp16 mma, volatile (GEMM)
__device__ __forceinline__ void mma_f16_v(float* d, const uint32_t* a,
                                          uint32_t b0, uint32_t b1) {
    asm volatile(
        "mma.sync.aligned.m16n8k16.row.col.f32.f16.f16.f32 "
        "{%0,%1,%2,%3}, {%4,%5,%6,%7}, {%8,%9}, {%0,%1,%2,%3};"
        : "+f"(d[0]), "+f"(d[1]), "+f"(d[2]), "+f"(d[3])
        : "r"(a[0]), "r"(a[1]), "r"(a[2]), "r"(a[3]), "r"(b0), "r"(b1));
}
// fp16 mma, non-volatile (attention)
__device__ __forceinline__ void mma_f16(float* d, const uint32_t* a,
                                        uint32_t b0, uint32_t b1) {
    asm("mma.sync.aligned.m16n8k16.row.col.f32.f16.f16.f32 "
        "{%0,%1,%2,%3}, {%4,%5,%6,%7}, {%8,%9}, {%0,%1,%2,%3};"
        : "+f"(d[0]), "+f"(d[1]), "+f"(d[2]), "+f"(d[3])
        : "r"(a[0]), "r"(a[1]), "r"(a[2]), "r"(a[3]), "r"(b0), "r"(b1));
}
__device__ __forceinline__ uint32_t h2u(__half2 v) {
    return *reinterpret_cast<uint32_t*>(&v);
}

// ---------------------------------------------------------------------------
// Conversion kernels
// ---------------------------------------------------------------------------
__global__ void cvt_f16_kernel(const float* __restrict__ in,
                               __half* __restrict__ out, int n)
{
    int i = (blockIdx.x * blockDim.x + threadIdx.x) * 8;
    if (i >= n) return;
    float4 a = *(const float4*)(in + i);
    float4 b = *(const float4*)(in + i + 4);
    __half h[8];
    h[0] = __float2half_rn(a.x); h[1] = __float2half_rn(a.y);
    h[2] = __float2half_rn(a.z); h[3] = __float2half_rn(a.w);
    h[4] = __float2half_rn(b.x); h[5] = __float2half_rn(b.y);
    h[6] = __float2half_rn(b.z); h[7] = __float2half_rn(b.w);
    *(uint4*)(out + i) = *(uint4*)h;
}

// W [K][N] row-major -> Wt fp16 [N][K]
__global__ void transpose_f16(const float* __restrict__ W,
                              __half* __restrict__ Tf, int K, int N)
{
    __shared__ float tile[32][33];
    int k0 = blockIdx.y * 32, n0 = blockIdx.x * 32;
    int tx = threadIdx.x, ty = threadIdx.y;
#pragma unroll
    for (int i = ty; i < 32; i += 8)
        tile[i][tx] = W[(size_t)(k0 + i) * N + n0 + tx];
    __syncthreads();
#pragma unroll
    for (int i = ty; i < 32; i += 8)
        Tf[(size_t)(n0 + i) * K + k0 + tx] = __float2half_rn(tile[tx][i]);
}

// ---------------------------------------------------------------------------
// mma.sync fp16 single-pass GEMM: C = A @ W^T + bias.
// Same 128x128 / BK=32 / 8-warp / 2-CTA-per-SM geometry.
// split_out=1: write fp16 (qkv); split_out=0: write fp32 (final output).
// ---------------------------------------------------------------------------
#define PAD 40
#define MAT_B (128 * PAD * 2)           // 10240
#define STAGE_B (2 * MAT_B)             // 20480 (A, B)
#define GEMM_SMEM (2 * STAGE_B)         // 40960
#define NCHUNK (GK / 32)

__global__ __launch_bounds__(256) void tc_gemm_mma(
    const __half* __restrict__ Af, const __half* __restrict__ Bf,
    const float* __restrict__ bias, float* __restrict__ Co,
    __half* __restrict__ Cf16, int N, int split_out)
{
    extern __shared__ char smem[];
    const uint32_t sb = smem_u32(smem);
    const int tid = threadIdx.x;
    const int wid = tid >> 5, lane = tid & 31;
    const int warp_m = wid >> 1, warp_n = wid & 1;
    const int m0 = blockIdx.y * 128, n0 = blockIdx.x * 128;

    const __half* srcs[2] = { Af + (size_t)m0 * GK, Bf + (size_t)n0 * GK };

    // 1024 16B segments per stage (2 matrices x 512), 4 per thread
    auto prefetch = [&](int c, int stage) {
        const int k0 = c * 32;
        const uint32_t so = sb + stage * STAGE_B;
#pragma unroll
        for (int msel = 0; msel < 2; msel++) {
#pragma unroll
            for (int i = 0; i < 2; i++) {
                int idx = tid + i * 256;
                int r = idx >> 2, seg = idx & 3;
                uint32_t dst = so + msel * MAT_B + (uint32_t)(r * PAD + seg * 8) * 2;
                cp_async16(dst, srcs[msel] + (size_t)r * GK + k0 + seg * 8);
            }
        }
    };

    float acc[2][8][4];
#pragma unroll
    for (int a = 0; a < 2; a++)
#pragma unroll
        for (int b = 0; b < 8; b++)
#pragma unroll
            for (int c = 0; c < 4; c++) acc[a][b][c] = 0.f;

    prefetch(0, 0);
    cp_commit();

    const int a_row = (lane & 15);
    const int a_col8 = (lane >> 4) << 3;
    const int b_tile = lane >> 3;
    const int b_rin = lane & 7;
    const int b_nrow = ((b_tile >> 1) << 3) + b_rin;
    const int b_kcol = (b_tile & 1) << 3;

    for (int c = 0; c < NCHUNK; c++) {
        const int stage = c & 1;
        if (c + 1 < NCHUNK) { prefetch(c + 1, stage ^ 1); cp_commit(); }
        if (c + 1 < NCHUNK) cp_wait<1>(); else cp_wait<0>();
        __syncthreads();

        const uint32_t so = sb + stage * STAGE_B;
#pragma unroll
        for (int ks = 0; ks < 2; ks++) {
            uint32_t aF[2][4];
#pragma unroll
            for (int mi = 0; mi < 2; mi++) {
                uint32_t off = (uint32_t)((warp_m * 32 + mi * 16 + a_row) * PAD
                                          + ks * 16 + a_col8) * 2;
                ldm_x4(aF[mi], so + off);
            }
#pragma unroll
            for (int nj = 0; nj < 4; nj++) {
                uint32_t bF[4];
                uint32_t off = (uint32_t)((warp_n * 64 + nj * 16 + b_nrow) * PAD
                                          + ks * 16 + b_kcol) * 2;
                ldm_x4(bF, so + MAT_B + off);
#pragma unroll
                for (int mi = 0; mi < 2; mi++) {
                    mma_f16_v(acc[mi][nj * 2],     aF[mi], bF[0], bF[1]);
                    mma_f16_v(acc[mi][nj * 2 + 1], aF[mi], bF[2], bF[3]);
                }
            }
        }
        __syncthreads();
    }

    const int r_base = m0 + warp_m * 32 + (lane >> 2);
    const int c_base = n0 + warp_n * 64 + (lane & 3) * 2;
    if (split_out) {
#pragma unroll
        for (int mi = 0; mi < 2; mi++) {
#pragma unroll
            for (int nj8 = 0; nj8 < 8; nj8++) {
                int col = c_base + nj8 * 8;
                float b0 = __ldg(bias + col), b1 = __ldg(bias + col + 1);
                int r0 = r_base + mi * 16;
                __half2 p0 = __float22half2_rn(
                    make_float2(acc[mi][nj8][0] + b0, acc[mi][nj8][1] + b1));
                __half2 p1 = __float22half2_rn(
                    make_float2(acc[mi][nj8][2] + b0, acc[mi][nj8][3] + b1));
                *(uint32_t*)(Cf16 + (size_t)r0 * N + col)       = h2u(p0);
                *(uint32_t*)(Cf16 + (size_t)(r0 + 8) * N + col) = h2u(p1);
            }
        }
    } else {
#pragma unroll
        for (int mi = 0; mi < 2; mi++) {
#pragma unroll
            for (int nj8 = 0; nj8 < 8; nj8++) {
                int col = c_base + nj8 * 8;
                float b0 = __ldg(bias + col), b1 = __ldg(bias + col + 1);
                int r0 = r_base + mi * 16;
                Co[(size_t)r0 * N + col]           = acc[mi][nj8][0] + b0;
                Co[(size_t)r0 * N + col + 1]       = acc[mi][nj8][1] + b1;
                Co[(size_t)(r0 + 8) * N + col]     = acc[mi][nj8][2] + b0;
                Co[(size_t)(r0 + 8) * N + col + 1] = acc[mi][nj8][3] + b1;
            }
        }
    }
}

// ---------------------------------------------------------------------------
// Tensor-core causal flash attention — single-pass fp16 (round-13/14, proven).
// ---------------------------------------------------------------------------
#define PADA 72
#define KTB  9216
#define QB   18432
#define KVS  (2 * KTB)
#define KVBASE QB
#define FLASH_SMEM (QB + 2 * KVS)       // 55296

__global__ __launch_bounds__(256) void flash_mma_kernel(
    const __half* __restrict__ qkvf, __half* __restrict__ yf)
{
    extern __shared__ __align__(16) char smem[];
    const uint32_t sb = smem_u32(smem);
    const int tid = threadIdx.x;
    const int wid = tid >> 5, lane = tid & 31;
    const int bh = blockIdx.x, b = bh >> 4, h = bh & 15;
    const int qt = (T_ / 128 - 1) - blockIdx.y;  // long CTAs first
    const int q0 = qt * 128;
    const size_t rowbase = (size_t)b * T_ * C3;

    auto fillKV = [&](int kt, int s) {
        const int k0 = kt * 64;
        const uint32_t so = sb + KVBASE + s * KVS;
#pragma unroll
        for (int i = 0; i < 4; i++) {
            int idx = tid + i * 256;
            int mat = idx >> 9;            // 0=K 1=V
            int rem = idx & 511;
            int r = rem >> 3, seg = rem & 7;
            const __half* src = qkvf + rowbase + (size_t)(k0 + r) * C3
                                + (mat ? 2 * C_ : C_) + h * D_ + seg * 8;
            cp_async16(so + (uint32_t)(mat * KTB + r * 144 + seg * 16), src);
        }
    };

    // ---- stage Q ----
    {
#pragma unroll
        for (int i = 0; i < 4; i++) {
            int idx = tid + i * 256;
            int r = idx >> 3, seg = idx & 7;
            const __half* src = qkvf + rowbase + (size_t)(q0 + r) * C3
                                + h * D_ + seg * 8;
            cp_async16(sb + (uint32_t)(r * 144 + seg * 16), src);
        }
    }
    cp_commit();
    fillKV(0, 0);
    cp_commit();

    const int a_row = lane & 15;
    const int a_col8 = (lane >> 4) << 3;
    const int b_tile = lane >> 3;
    const int b_nrow = ((b_tile >> 1) << 3) + (lane & 7);
    const int b_kcol = (b_tile & 1) << 3;
    const int v_krow = ((b_tile & 1) << 3) + (lane & 7);
    const int v_ncol = (b_tile >> 1) << 3;

    cp_wait<1>();
    __syncthreads();

    uint32_t aQ[4][4];
#pragma unroll
    for (int ks = 0; ks < 4; ks++) {
        uint32_t off = (uint32_t)((wid * 16 + a_row) * PADA + ks * 16 + a_col8) * 2;
        ldm_x4(aQ[ks], sb + off);
    }

    float oacc[8][4];
#pragma unroll
    for (int i = 0; i < 8; i++)
#pragma unroll
        for (int j = 0; j < 4; j++) oacc[i][j] = 0.f;
    float mrow[2] = {-1e30f, -1e30f};
    float lrow[2] = {0.f, 0.f};

    const int ntiles = 2 * (qt + 1);
    for (int kt = 0; kt < ntiles; kt++) {
        const int s = kt & 1;
        const int k0 = kt * 64;
        __syncthreads();
        if (kt + 1 < ntiles) { fillKV(kt + 1, s ^ 1); cp_commit(); }
        if (kt + 1 < ntiles) cp_wait<1>(); else cp_wait<0>();
        __syncthreads();

        const uint32_t kvso = sb + KVBASE + s * KVS;

        // ---- S = Q @ K^T ----
        float sacc[8][4];
#pragma unroll
        for (int i = 0; i < 8; i++)
#pragma unroll
            for (int j = 0; j < 4; j++) sacc[i][j] = 0.f;
#pragma unroll
        for (int ks = 0; ks < 4; ks++) {
            uint32_t bK[4];
#pragma unroll
            for (int nj = 0; nj < 4; nj++) {
                uint32_t off = (uint32_t)((nj * 16 + b_nrow) * PADA
                                          + ks * 16 + b_kcol) * 2;
                ldm_x4(bK, kvso + off);
                mma_f16(sacc[nj * 2],     aQ[ks], bK[0], bK[1]);
                mma_f16(sacc[nj * 2 + 1], aQ[ks], bK[2], bK[3]);
            }
        }
#pragma unroll
        for (int nb = 0; nb < 8; nb++) {
            sacc[nb][0] *= 0.125f; sacc[nb][1] *= 0.125f;
            sacc[nb][2] *= 0.125f; sacc[nb][3] *= 0.125f;
        }

        // ---- causal mask (last two tiles only) ----
        if (k0 >= q0) {
            const int qg = q0 + wid * 16 + (lane >> 2);
            const int cg = k0 + (lane & 3) * 2;
#pragma unroll
            for (int nb = 0; nb < 8; nb++) {
                int col = cg + nb * 8;
                if (col > qg)          sacc[nb][0] = -1e30f;
                if (col + 1 > qg)      sacc[nb][1] = -1e30f;
                if (col > qg + 8)      sacc[nb][2] = -1e30f;
                if (col + 1 > qg + 8)  sacc[nb][3] = -1e30f;
            }
        }

        // ---- online softmax ----
        float mn0 = mrow[0], mn1 = mrow[1];
#pragma unroll
        for (int nb = 0; nb < 8; nb++) {
            mn0 = fmaxf(mn0, fmaxf(sacc[nb][0], sacc[nb][1]));
            mn1 = fmaxf(mn1, fmaxf(sacc[nb][2], sacc[nb][3]));
        }
        mn0 = fmaxf(mn0, __shfl_xor_sync(0xFFFFFFFF, mn0, 1));
        mn0 = fmaxf(mn0, __shfl_xor_sync(0xFFFFFFFF, mn0, 2));
        mn1 = fmaxf(mn1, __shfl_xor_sync(0xFFFFFFFF, mn1, 1));
        mn1 = fmaxf(mn1, __shfl_xor_sync(0xFFFFFFFF, mn1, 2));
        const float corr0 = __expf(mrow[0] - mn0);
        const float corr1 = __expf(mrow[1] - mn1);
        mrow[0] = mn0; mrow[1] = mn1;

        float ps0 = 0.f, ps1 = 0.f;
#pragma unroll
        for (int nb = 0; nb < 8; nb++) {
            sacc[nb][0] = __expf(sacc[nb][0] - mn0);
            sacc[nb][1] = __expf(sacc[nb][1] - mn0);
            sacc[nb][2] = __expf(sacc[nb][2] - mn1);
            sacc[nb][3] = __expf(sacc[nb][3] - mn1);
            ps0 += sacc[nb][0] + sacc[nb][1];
            ps1 += sacc[nb][2] + sacc[nb][3];
        }
        ps0 += __shfl_xor_sync(0xFFFFFFFF, ps0, 1);
        ps0 += __shfl_xor_sync(0xFFFFFFFF, ps0, 2);
        ps1 += __shfl_xor_sync(0xFFFFFFFF, ps1, 1);
        ps1 += __shfl_xor_sync(0xFFFFFFFF, ps1, 2);
        lrow[0] = lrow[0] * corr0 + ps0;
        lrow[1] = lrow[1] * corr1 + ps1;
#pragma unroll
        for (int nb = 0; nb < 8; nb++) {
            oacc[nb][0] *= corr0; oacc[nb][1] *= corr0;
            oacc[nb][2] *= corr1; oacc[nb][3] *= corr1;
        }

        // ---- O += P @ V ----
#pragma unroll
        for (int ks = 0; ks < 4; ks++) {
            uint32_t pF[4];
            pF[0] = h2u(__float22half2_rn(
                make_float2(sacc[2 * ks][0], sacc[2 * ks][1])));
            pF[1] = h2u(__float22half2_rn(
                make_float2(sacc[2 * ks][2], sacc[2 * ks][3])));
            pF[2] = h2u(__float22half2_rn(
                make_float2(sacc[2 * ks + 1][0], sacc[2 * ks + 1][1])));
            pF[3] = h2u(__float22half2_rn(
                make_float2(sacc[2 * ks + 1][2], sacc[2 * ks + 1][3])));
#pragma unroll
            for (int nj = 0; nj < 4; nj++) {
                uint32_t bV[4];
                uint32_t off = (uint32_t)((ks * 16 + v_krow) * PADA
                                          + nj * 16 + v_ncol) * 2;
                ldm_x4_trans(bV, kvso + KTB + off);
                mma_f16(oacc[nj * 2],     pF, bV[0], bV[1]);
                mma_f16(oacc[nj * 2 + 1], pF, bV[2], bV[3]);
            }
        }
    }

    // ---- normalize and write y as single fp16 ----
    const float inv0 = 1.f / lrow[0];
    const float inv1 = 1.f / lrow[1];
    const int rg = q0 + wid * 16 + (lane >> 2);
    const size_t e0 = ((size_t)b * T_ + rg) * C_ + h * D_ + (lane & 3) * 2;
#pragma unroll
    for (int nb = 0; nb < 8; nb++) {
        __half2 o0 = __float22half2_rn(
            make_float2(oacc[nb][0] * inv0, oacc[nb][1] * inv0));
        __half2 o1 = __float22half2_rn(
            make_float2(oacc[nb][2] * inv1, oacc[nb][3] * inv1));
        *(uint32_t*)(yf + e0 + nb * 8)          = h2u(o0);
        *(uint32_t*)(yf + e0 + 8 * C_ + nb * 8) = h2u(o1);
    }
}

// ---------------------------------------------------------------------------
extern "C" void kernel_launch(void* const* d_in, const int* in_sizes, int n_in,
                              void* d_out, int out_size)
{
    const float* x      = (const float*)d_in[0];
    const float* W_attn = (const float*)d_in[1];
    const float* b_attn = (const float*)d_in[2];
    const float* W_proj = (const float*)d_in[3];
    const float* b_proj = (const float*)d_in[4];
    float* out = (float*)d_out;

    __half *qkvf, *xf, *yf, *waf, *wpf;
    cudaGetSymbolAddress((void**)&qkvf, g_qkvf);
    cudaGetSymbolAddress((void**)&xf, g_xf);
    cudaGetSymbolAddress((void**)&yf, g_yf);
    cudaGetSymbolAddress((void**)&waf, g_waf);
    cudaGetSymbolAddress((void**)&wpf, g_wpf);

    cudaFuncSetAttribute(tc_gemm_mma, cudaFuncAttributeMaxDynamicSharedMemorySize,
                         GEMM_SMEM);
    cudaFuncSetAttribute(flash_mma_kernel,
                         cudaFuncAttributeMaxDynamicSharedMemorySize, FLASH_SMEM);

    const int NTOK_EL = M_TOK * C_;

    // 1) x -> fp16
    cvt_f16_kernel<<<NTOK_EL / 8 / 256, 256>>>(x, xf, NTOK_EL);
    // 2) transpose weights -> fp16
    transpose_f16<<<dim3(C3 / 32, C_ / 32), dim3(32, 8)>>>(W_attn, waf, C_, C3);
    transpose_f16<<<dim3(C_ / 32, C_ / 32), dim3(32, 8)>>>(W_proj, wpf, C_, C_);
    // 3) QKV GEMM (single-pass fp16) -> qkv fp16
    tc_gemm_mma<<<dim3(C3 / 128, M_TOK / 128), 256, GEMM_SMEM>>>(
        xf, waf, b_attn, nullptr, qkvf, C3, 1);
    // 4) causal flash attention (single-pass fp16 tensor cores)
    flash_mma_kernel<<<dim3(B_ * H_, T_ / 128), 256, FLASH_SMEM>>>(qkvf, yf);
    // 5) proj GEMM (single-pass fp16) -> d_out fp32
    tc_gemm_mma<<<dim3(C_ / 128, M_TOK / 128), 256, GEMM_SMEM>>>(
        yf, wpf, b_proj, out, nullptr, C_, 0);
}

// round 16
// speedup vs baseline: 2.7901x; 1.0941x over previous
#include <cuda_runtime.h>
#include <cuda_bf16.h>
#include <cuda_fp16.h>
#include <cstdint>
#include <cstddef>

// Problem constants
#define B_  4
#define T_  2048
#define C_  1024
#define H_  16
#define D_  64
#define M_TOK (B_ * T_)      // 8192
#define C3 (3 * C_)          // 3072
#define GK 1024              // K of both GEMMs

// ---------------------------------------------------------------------------
// Scratch (device globals; allocation in kernel_launch is forbidden)
// ---------------------------------------------------------------------------
__device__ __half g_qkvf[(size_t)M_TOK * C3];   // qkv fp16 (from GEMM epi)
__device__ __half g_xf[(size_t)M_TOK * C_];     // x fp16
__device__ __half g_yf[(size_t)M_TOK * C_];     // attention out fp16
__device__ __half g_waf[(size_t)C3 * C_];       // W_attn^T fp16 [3C][C]
__device__ __half g_wpf[(size_t)C_ * C_];       // W_proj^T fp16 [C][C]

// ---------------------------------------------------------------------------
// PTX helpers
// ---------------------------------------------------------------------------
__device__ __forceinline__ uint32_t smem_u32(const void* p) {
    uint32_t a;
    asm("{ .reg .u64 t; cvta.to.shared.u64 t, %1; cvt.u32.u64 %0, t; }"
        : "=r"(a) : "l"(p));
    return a;
}
__device__ __forceinline__ void cp_async16(uint32_t dst, const void* src) {
    asm volatile("cp.async.cg.shared.global [%0], [%1], 16;"
                 :: "r"(dst), "l"(src) : "memory");
}
__device__ __forceinline__ void cp_commit() {
    asm volatile("cp.async.commit_group;" ::: "memory");
}
template <int N>
__device__ __forceinline__ void cp_wait() {
    asm volatile("cp.async.wait_group %0;" :: "n"(N) : "memory");
}
__device__ __forceinline__ void ldm_x4(uint32_t* r, uint32_t addr) {
    asm volatile("ldmatrix.sync.aligned.m8n8.x4.shared.b16 {%0,%1,%2,%3}, [%4];"
                 : "=r"(r[0]), "=r"(r[1]), "=r"(r[2]), "=r"(r[3]) : "r"(addr));
}
__device__ __forceinline__ void ldm_x4_trans(uint32_t* r, uint32_t addr) {
    asm volatile("ldmatrix.sync.aligned.m8n8.x4.trans.shared.b16 {%0,%1,%2,%3}, [%4];"
                 : "=r"(r[0]), "=r"(r[1]), "=r"(r[2]), "=r"(r[3]) : "r"(addr));
}
// fp16 mma, volatile (GEMM)
__device__ __forceinline__ void mma_f16_v(float* d, const uint32_t* a,
                                          uint32_t b0, uint32_t b1) {
    asm volatile(
        "mma.sync.aligned.m16n8k16.row.col.f32.f16.f16.f32 "
        "{%0,%1,%2,%3}, {%4,%5,%6,%7}, {%8,%9}, {%0,%1,%2,%3};"
        : "+f"(d[0]), "+f"(d[1]), "+f"(d[2]), "+f"(d[3])
        : "r"(a[0]), "r"(a[1]), "r"(a[2]), "r"(a[3]), "r"(b0), "r"(b1));
}
// fp16 mma, non-volatile (attention)
__device__ __forceinline__ void mma_f16(float* d, const uint32_t* a,
                                        uint32_t b0, uint32_t b1) {
    asm("mma.sync.aligned.m16n8k16.row.col.f32.f16.f16.f32 "
        "{%0,%1,%2,%3}, {%4,%5,%6,%7}, {%8,%9}, {%0,%1,%2,%3};"
        : "+f"(d[0]), "+f"(d[1]), "+f"(d[2]), "+f"(d[3])
        : "r"(a[0]), "r"(a[1]), "r"(a[2]), "r"(a[3]), "r"(b0), "r"(b1));
}
__device__ __forceinline__ uint32_t h2u(__half2 v) {
    return *reinterpret_cast<uint32_t*>(&v);
}

// ---------------------------------------------------------------------------
// Conversion kernels
// ---------------------------------------------------------------------------
__global__ void cvt_f16_kernel(const float* __restrict__ in,
                               __half* __restrict__ out, int n)
{
    int i = (blockIdx.x * blockDim.x + threadIdx.x) * 8;
    if (i >= n) return;
    float4 a = *(const float4*)(in + i);
    float4 b = *(const float4*)(in + i + 4);
    __half h[8];
    h[0] = __float2half_rn(a.x); h[1] = __float2half_rn(a.y);
    h[2] = __float2half_rn(a.z); h[3] = __float2half_rn(a.w);
    h[4] = __float2half_rn(b.x); h[5] = __float2half_rn(b.y);
    h[6] = __float2half_rn(b.z); h[7] = __float2half_rn(b.w);
    *(uint4*)(out + i) = *(uint4*)h;
}

// W [K][N] row-major -> Wt fp16 [N][K]
__global__ void transpose_f16(const float* __restrict__ W,
                              __half* __restrict__ Tf, int K, int N)
{
    __shared__ float tile[32][33];
    int k0 = blockIdx.y * 32, n0 = blockIdx.x * 32;
    int tx = threadIdx.x, ty = threadIdx.y;
#pragma unroll
    for (int i = ty; i < 32; i += 8)
        tile[i][tx] = W[(size_t)(k0 + i) * N + n0 + tx];
    __syncthreads();
#pragma unroll
    for (int i = ty; i < 32; i += 8)
        Tf[(size_t)(n0 + i) * K + k0 + tx] = __float2half_rn(tile[tx][i]);
}

// ---------------------------------------------------------------------------
// mma.sync fp16 single-pass GEMM: C = A @ W^T + bias.
// BK=64 (16 chunks): halves barrier/prefetch overhead per MMA vs BK=32.
// Rows padded to 72 halves (144 B stride — conflict-free, proven in flash).
// Global K accumulation order identical to round 15 -> bit-identical result.
// ---------------------------------------------------------------------------
#define PAD 72
#define MAT_B (128 * PAD * 2)           // 18432
#define STAGE_B (2 * MAT_B)             // 36864 (A, B)
#define GEMM_SMEM (2 * STAGE_B)         // 73728
#define NCHUNK (GK / 64)                // 16

__global__ __launch_bounds__(256) void tc_gemm_mma(
    const __half* __restrict__ Af, const __half* __restrict__ Bf,
    const float* __restrict__ bias, float* __restrict__ Co,
    __half* __restrict__ Cf16, int N, int split_out)
{
    extern __shared__ char smem[];
    const uint32_t sb = smem_u32(smem);
    const int tid = threadIdx.x;
    const int wid = tid >> 5, lane = tid & 31;
    const int warp_m = wid >> 1, warp_n = wid & 1;
    const int m0 = blockIdx.y * 128, n0 = blockIdx.x * 128;

    const __half* srcs[2] = { Af + (size_t)m0 * GK, Bf + (size_t)n0 * GK };

    // per stage: 2 matrices x 128 rows x 8 16B-segments = 2048 cp.async, 8/thread
    auto prefetch = [&](int c, int stage) {
        const int k0 = c * 64;
        const uint32_t so = sb + stage * STAGE_B;
#pragma unroll
        for (int msel = 0; msel < 2; msel++) {
#pragma unroll
            for (int i = 0; i < 4; i++) {
                int idx = tid + i * 256;        // 0..1023
                int r = idx >> 3, seg = idx & 7;
                uint32_t dst = so + msel * MAT_B + (uint32_t)(r * PAD + seg * 8) * 2;
                cp_async16(dst, srcs[msel] + (size_t)r * GK + k0 + seg * 8);
            }
        }
    };

    float acc[2][8][4];
#pragma unroll
    for (int a = 0; a < 2; a++)
#pragma unroll
        for (int b = 0; b < 8; b++)
#pragma unroll
            for (int c = 0; c < 4; c++) acc[a][b][c] = 0.f;

    prefetch(0, 0);
    cp_commit();

    const int a_row = (lane & 15);
    const int a_col8 = (lane >> 4) << 3;
    const int b_tile = lane >> 3;
    const int b_rin = lane & 7;
    const int b_nrow = ((b_tile >> 1) << 3) + b_rin;
    const int b_kcol = (b_tile & 1) << 3;

    for (int c = 0; c < NCHUNK; c++) {
        const int stage = c & 1;
        if (c + 1 < NCHUNK) { prefetch(c + 1, stage ^ 1); cp_commit(); }
        if (c + 1 < NCHUNK) cp_wait<1>(); else cp_wait<0>();
        __syncthreads();

        const uint32_t so = sb + stage * STAGE_B;
#pragma unroll
        for (int ks = 0; ks < 4; ks++) {
            uint32_t aF[2][4];
#pragma unroll
            for (int mi = 0; mi < 2; mi++) {
                uint32_t off = (uint32_t)((warp_m * 32 + mi * 16 + a_row) * PAD
                                          + ks * 16 + a_col8) * 2;
                ldm_x4(aF[mi], so + off);
            }
#pragma unroll
            for (int nj = 0; nj < 4; nj++) {
                uint32_t bF[4];
                uint32_t off = (uint32_t)((warp_n * 64 + nj * 16 + b_nrow) * PAD
                                          + ks * 16 + b_kcol) * 2;
                ldm_x4(bF, so + MAT_B + off);
#pragma unroll
                for (int mi = 0; mi < 2; mi++) {
                    mma_f16_v(acc[mi][nj * 2],     aF[mi], bF[0], bF[1]);
                    mma_f16_v(acc[mi][nj * 2 + 1], aF[mi], bF[2], bF[3]);
                }
            }
        }
        __syncthreads();
    }

    const int r_base = m0 + warp_m * 32 + (lane >> 2);
    const int c_base = n0 + warp_n * 64 + (lane & 3) * 2;
    if (split_out) {
#pragma unroll
        for (int mi = 0; mi < 2; mi++) {
#pragma unroll
            for (int nj8 = 0; nj8 < 8; nj8++) {
                int col = c_base + nj8 * 8;
                float b0 = __ldg(bias + col), b1 = __ldg(bias + col + 1);
                int r0 = r_base + mi * 16;
                __half2 p0 = __float22half2_rn(
                    make_float2(acc[mi][nj8][0] + b0, acc[mi][nj8][1] + b1));
                __half2 p1 = __float22half2_rn(
                    make_float2(acc[mi][nj8][2] + b0, acc[mi][nj8][3] + b1));
                *(uint32_t*)(Cf16 + (size_t)r0 * N + col)       = h2u(p0);
                *(uint32_t*)(Cf16 + (size_t)(r0 + 8) * N + col) = h2u(p1);
            }
        }
    } else {
#pragma unroll
        for (int mi = 0; mi < 2; mi++) {
#pragma unroll
            for (int nj8 = 0; nj8 < 8; nj8++) {
                int col = c_base + nj8 * 8;
                float b0 = __ldg(bias + col), b1 = __ldg(bias + col + 1);
                int r0 = r_base + mi * 16;
                Co[(size_t)r0 * N + col]           = acc[mi][nj8][0] + b0;
                Co[(size_t)r0 * N + col + 1]       = acc[mi][nj8][1] + b1;
                Co[(size_t)(r0 + 8) * N + col]     = acc[mi][nj8][2] + b0;
                Co[(size_t)(r0 + 8) * N + col + 1] = acc[mi][nj8][3] + b1;
            }
        }
    }
}

// ---------------------------------------------------------------------------
// Tensor-core causal flash attention — single-pass fp16 (round-13/14, proven,
// unchanged).
// ---------------------------------------------------------------------------
#define PADA 72
#define KTB  9216
#define QB   18432
#define KVS  (2 * KTB)
#define KVBASE QB
#define FLASH_SMEM (QB + 2 * KVS)       // 55296

__global__ __launch_bounds__(256) void flash_mma_kernel(
    const __half* __restrict__ qkvf, __half* __restrict__ yf)
{
    extern __shared__ __align__(16) char smem[];
    const uint32_t sb = smem_u32(smem);
    const int tid = threadIdx.x;
    const int wid = tid >> 5, lane = tid & 31;
    const int bh = blockIdx.x, b = bh >> 4, h = bh & 15;
    const int qt = (T_ / 128 - 1) - blockIdx.y;  // long CTAs first
    const int q0 = qt * 128;
    const size_t rowbase = (size_t)b * T_ * C3;

    auto fillKV = [&](int kt, int s) {
        const int k0 = kt * 64;
        const uint32_t so = sb + KVBASE + s * KVS;
#pragma unroll
        for (int i = 0; i < 4; i++) {
            int idx = tid + i * 256;
            int mat = idx >> 9;            // 0=K 1=V
            int rem = idx & 511;
            int r = rem >> 3, seg = rem & 7;
            const __half* src = qkvf + rowbase + (size_t)(k0 + r) * C3
                                + (mat ? 2 * C_ : C_) + h * D_ + seg * 8;
            cp_async16(so + (uint32_t)(mat * KTB + r * 144 + seg * 16), src);
        }
    };

    // ---- stage Q ----
    {
#pragma unroll
        for (int i = 0; i < 4; i++) {
            int idx = tid + i * 256;
            int r = idx >> 3, seg = idx & 7;
            const __half* src = qkvf + rowbase + (size_t)(q0 + r) * C3
                                + h * D_ + seg * 8;
            cp_async16(sb + (uint32_t)(r * 144 + seg * 16), src);
        }
    }
    cp_commit();
    fillKV(0, 0);
    cp_commit();

    const int a_row = lane & 15;
    const int a_col8 = (lane >> 4) << 3;
    const int b_tile = lane >> 3;
    const int b_nrow = ((b_tile >> 1) << 3) + (lane & 7);
    const int b_kcol = (b_tile & 1) << 3;
    const int v_krow = ((b_tile & 1) << 3) + (lane & 7);
    const int v_ncol = (b_tile >> 1) << 3;

    cp_wait<1>();
    __syncthreads();

    uint32_t aQ[4][4];
#pragma unroll
    for (int ks = 0; ks < 4; ks++) {
        uint32_t off = (uint32_t)((wid * 16 + a_row) * PADA + ks * 16 + a_col8) * 2;
        ldm_x4(aQ[ks], sb + off);
    }

    float oacc[8][4];
#pragma unroll
    for (int i = 0; i < 8; i++)
#pragma unroll
        for (int j = 0; j < 4; j++) oacc[i][j] = 0.f;
    float mrow[2] = {-1e30f, -1e30f};
    float lrow[2] = {0.f, 0.f};

    const int ntiles = 2 * (qt + 1);
    for (int kt = 0; kt < ntiles; kt++) {
        const int s = kt & 1;
        const int k0 = kt * 64;
        __syncthreads();
        if (kt + 1 < ntiles) { fillKV(kt + 1, s ^ 1); cp_commit(); }
        if (kt + 1 < ntiles) cp_wait<1>(); else cp_wait<0>();
        __syncthreads();

        const uint32_t kvso = sb + KVBASE + s * KVS;

        // ---- S = Q @ K^T ----
        float sacc[8][4];
#pragma unroll
        for (int i = 0; i < 8; i++)
#pragma unroll
            for (int j = 0; j < 4; j++) sacc[i][j] = 0.f;
#pragma unroll
        for (int ks = 0; ks < 4; ks++) {
            uint32_t bK[4];
#pragma unroll
            for (int nj = 0; nj < 4; nj++) {
                uint32_t off = (uint32_t)((nj * 16 + b_nrow) * PADA
                                          + ks * 16 + b_kcol) * 2;
                ldm_x4(bK, kvso + off);
                mma_f16(sacc[nj * 2],     aQ[ks], bK[0], bK[1]);
                mma_f16(sacc[nj * 2 + 1], aQ[ks], bK[2], bK[3]);
            }
        }
#pragma unroll
        for (int nb = 0; nb < 8; nb++) {
            sacc[nb][0] *= 0.125f; sacc[nb][1] *= 0.125f;
            sacc[nb][2] *= 0.125f; sacc[nb][3] *= 0.125f;
        }

        // ---- causal mask (last two tiles only) ----
        if (k0 >= q0) {
            const int qg = q0 + wid * 16 + (lane >> 2);
            const int cg = k0 + (lane & 3) * 2;
#pragma unroll
            for (int nb = 0; nb < 8; nb++) {
                int col = cg + nb * 8;
                if (col > qg)          sacc[nb][0] = -1e30f;
                if (col + 1 > qg)      sacc[nb][1] = -1e30f;
                if (col > qg + 8)      sacc[nb][2] = -1e30f;
                if (col + 1 > qg + 8)  sacc[nb][3] = -1e30f;
            }
        }

        // ---- online softmax ----
        float mn0 = mrow[0], mn1 = mrow[1];
#pragma unroll
        for (int nb = 0; nb < 8; nb++) {
            mn0 = fmaxf(mn0, fmaxf(sacc[nb][0], sacc[nb][1]));
            mn1 = fmaxf(mn1, fmaxf(sacc[nb][2], sacc[nb][3]));
        }
        mn0 = fmaxf(mn0, __shfl_xor_sync(0xFFFFFFFF, mn0, 1));
        mn0 = fmaxf(mn0, __shfl_xor_sync(0xFFFFFFFF, mn0, 2));
        mn1 = fmaxf(mn1, __shfl_xor_sync(0xFFFFFFFF, mn1, 1));
        mn1 = fmaxf(mn1, __shfl_xor_sync(0xFFFFFFFF, mn1, 2));
        const float corr0 = __expf(mrow[0] - mn0);
        const float corr1 = __expf(mrow[1] - mn1);
        mrow[0] = mn0; mrow[1] = mn1;

        float ps0 = 0.f, ps1 = 0.f;
#pragma unroll
        for (int nb = 0; nb < 8; nb++) {
            sacc[nb][0] = __expf(sacc[nb][0] - mn0);
            sacc[nb][1] = __expf(sacc[nb][1] - mn0);
            sacc[nb][2] = __expf(sacc[nb][2] - mn1);
            sacc[nb][3] = __expf(sacc[nb][3] - mn1);
            ps0 += sacc[nb][0] + sacc[nb][1];
            ps1 += sacc[nb][2] + sacc[nb][3];
        }
        ps0 += __shfl_xor_sync(0xFFFFFFFF, ps0, 1);
        ps0 += __shfl_xor_sync(0xFFFFFFFF, ps0, 2);
        ps1 += __shfl_xor_sync(0xFFFFFFFF, ps1, 1);
        ps1 += __shfl_xor_sync(0xFFFFFFFF, ps1, 2);
        lrow[0] = lrow[0] * corr0 + ps0;
        lrow[1] = lrow[1] * corr1 + ps1;
#pragma unroll
        for (int nb = 0; nb < 8; nb++) {
            oacc[nb][0] *= corr0; oacc[nb][1] *= corr0;
            oacc[nb][2] *= corr1; oacc[nb][3] *= corr1;
        }

        // ---- O += P @ V ----
#pragma unroll
        for (int ks = 0; ks < 4; ks++) {
            uint32_t pF[4];
            pF[0] = h2u(__float22half2_rn(
                make_float2(sacc[2 * ks][0], sacc[2 * ks][1])));
            pF[1] = h2u(__float22half2_rn(
                make_float2(sacc[2 * ks][2], sacc[2 * ks][3])));
            pF[2] = h2u(__float22half2_rn(
                make_float2(sacc[2 * ks + 1][0], sacc[2 * ks + 1][1])));
            pF[3] = h2u(__float22half2_rn(
                make_float2(sacc[2 * ks + 1][2], sacc[2 * ks + 1][3])));
#pragma unroll
            for (int nj = 0; nj < 4; nj++) {
                uint32_t bV[4];
                uint32_t off = (uint32_t)((ks * 16 + v_krow) * PADA
                                          + nj * 16 + v_ncol) * 2;
                ldm_x4_trans(bV, kvso + KTB + off);
                mma_f16(oacc[nj * 2],     pF, bV[0], bV[1]);
                mma_f16(oacc[nj * 2 + 1], pF, bV[2], bV[3]);
            }
        }
    }

    // ---- normalize and write y as single fp16 ----
    const float inv0 = 1.f / lrow[0];
    const float inv1 = 1.f / lrow[1];
    const int rg = q0 + wid * 16 + (lane >> 2);
    const size_t e0 = ((size_t)b * T_ + rg) * C_ + h * D_ + (lane & 3) * 2;
#pragma unroll
    for (int nb = 0; nb < 8; nb++) {
        __half2 o0 = __float22half2_rn(
            make_float2(oacc[nb][0] * inv0, oacc[nb][1] * inv0));
        __half2 o1 = __float22half2_rn(
            make_float2(oacc[nb][2] * inv1, oacc[nb][3] * inv1));
        *(uint32_t*)(yf + e0 + nb * 8)          = h2u(o0);
        *(uint32_t*)(yf + e0 + 8 * C_ + nb * 8) = h2u(o1);
    }
}

// ---------------------------------------------------------------------------
extern "C" void kernel_launch(void* const* d_in, const int* in_sizes, int n_in,
                              void* d_out, int out_size)
{
    const float* x      = (const float*)d_in[0];
    const float* W_attn = (const float*)d_in[1];
    const float* b_attn = (const float*)d_in[2];
    const float* W_proj = (const float*)d_in[3];
    const float* b_proj = (const float*)d_in[4];
    float* out = (float*)d_out;

    __half *qkvf, *xf, *yf, *waf, *wpf;
    cudaGetSymbolAddress((void**)&qkvf, g_qkvf);
    cudaGetSymbolAddress((void**)&xf, g_xf);
    cudaGetSymbolAddress((void**)&yf, g_yf);
    cudaGetSymbolAddress((void**)&waf, g_waf);
    cudaGetSymbolAddress((void**)&wpf, g_wpf);

    cudaFuncSetAttribute(tc_gemm_mma, cudaFuncAttributeMaxDynamicSharedMemorySize,
                         GEMM_SMEM);
    cudaFuncSetAttribute(flash_mma_kernel,
                         cudaFuncAttributeMaxDynamicSharedMemorySize, FLASH_SMEM);

    const int NTOK_EL = M_TOK * C_;

    // 1) x -> fp16
    cvt_f16_kernel<<<NTOK_EL / 8 / 256, 256>>>(x, xf, NTOK_EL);
    // 2) transpose weights -> fp16
    transpose_f16<<<dim3(C3 / 32, C_ / 32), dim3(32, 8)>>>(W_attn, waf, C_, C3);
    transpose_f16<<<dim3(C_ / 32, C_ / 32), dim3(32, 8)>>>(W_proj, wpf, C_, C_);
    // 3) QKV GEMM (single-pass fp16, BK=64) -> qkv fp16
    tc_gemm_mma<<<dim3(C3 / 128, M_TOK / 128), 256, GEMM_SMEM>>>(
        xf, waf, b_attn, nullptr, qkvf, C3, 1);
    // 4) causal flash attention (single-pass fp16 tensor cores)
    flash_mma_kernel<<<dim3(B_ * H_, T_ / 128), 256, FLASH_SMEM>>>(qkvf, yf);
    // 5) proj GEMM (single-pass fp16, BK=64) -> d_out fp32
    tc_gemm_mma<<<dim3(C_ / 128, M_TOK / 128), 256, GEMM_SMEM>>>(
        yf, wpf, b_proj, out, nullptr, C_, 0);
}

// round 17
// speedup vs baseline: 2.8668x; 1.0275x over previous
#include <cuda_runtime.h>
#include <cuda_bf16.h>
#include <cuda_fp16.h>
#include <cstdint>
#include <cstddef>

// Problem constants
#define B_  4
#define T_  2048
#define C_  1024
#define H_  16
#define D_  64
#define M_TOK (B_ * T_)      // 8192
#define C3 (3 * C_)          // 3072
#define GK 1024              // K of both GEMMs

// ---------------------------------------------------------------------------
// Scratch (device globals; allocation in kernel_launch is forbidden)
// ---------------------------------------------------------------------------
__device__ __half g_qkvf[(size_t)M_TOK * C3];   // qkv fp16 (from GEMM epi)
__device__ __half g_xf[(size_t)M_TOK * C_];     // x fp16
__device__ __half g_yf[(size_t)M_TOK * C_];     // attention out fp16
__device__ __half g_waf[(size_t)C3 * C_];       // W_attn^T fp16 [3C][C]
__device__ __half g_wpf[(size_t)C_ * C_];       // W_proj^T fp16 [C][C]

// ---------------------------------------------------------------------------
// PTX helpers
// ---------------------------------------------------------------------------
__device__ __forceinline__ uint32_t smem_u32(const void* p) {
    uint32_t a;
    asm("{ .reg .u64 t; cvta.to.shared.u64 t, %1; cvt.u32.u64 %0, t; }"
        : "=r"(a) : "l"(p));
    return a;
}
__device__ __forceinline__ void cp_async16(uint32_t dst, const void* src) {
    asm volatile("cp.async.cg.shared.global [%0], [%1], 16;"
                 :: "r"(dst), "l"(src) : "memory");
}
__device__ __forceinline__ void cp_commit() {
    asm volatile("cp.async.commit_group;" ::: "memory");
}
template <int N>
__device__ __forceinline__ void cp_wait() {
    asm volatile("cp.async.wait_group %0;" :: "n"(N) : "memory");
}
__device__ __forceinline__ void ldm_x4(uint32_t* r, uint32_t addr) {
    asm volatile("ldmatrix.sync.aligned.m8n8.x4.shared.b16 {%0,%1,%2,%3}, [%4];"
                 : "=r"(r[0]), "=r"(r[1]), "=r"(r[2]), "=r"(r[3]) : "r"(addr));
}
__device__ __forceinline__ void ldm_x4_trans(uint32_t* r, uint32_t addr) {
    asm volatile("ldmatrix.sync.aligned.m8n8.x4.trans.shared.b16 {%0,%1,%2,%3}, [%4];"
                 : "=r"(r[0]), "=r"(r[1]), "=r"(r[2]), "=r"(r[3]) : "r"(addr));
}
// fp16 mma, volatile (GEMM)
__device__ __forceinline__ void mma_f16_v(float* d, const uint32_t* a,
                                          uint32_t b0, uint32_t b1) {
    asm volatile(
        "mma.sync.aligned.m16n8k16.row.col.f32.f16.f16.f32 "
        "{%0,%1,%2,%3}, {%4,%5,%6,%7}, {%8,%9}, {%0,%1,%2,%3};"
        : "+f"(d[0]), "+f"(d[1]), "+f"(d[2]), "+f"(d[3])
        : "r"(a[0]), "r"(a[1]), "r"(a[2]), "r"(a[3]), "r"(b0), "r"(b1));
}
// fp16 mma, non-volatile (attention)
__device__ __forceinline__ void mma_f16(float* d, const uint32_t* a,
                                        uint32_t b0, uint32_t b1) {
    asm("mma.sync.aligned.m16n8k16.row.col.f32.f16.f16.f32 "
        "{%0,%1,%2,%3}, {%4,%5,%6,%7}, {%8,%9}, {%0,%1,%2,%3};"
        : "+f"(d[0]), "+f"(d[1]), "+f"(d[2]), "+f"(d[3])
        : "r"(a[0]), "r"(a[1]), "r"(a[2]), "r"(a[3]), "r"(b0), "r"(b1));
}
__device__ __forceinline__ uint32_t h2u(__half2 v) {
    return *reinterpret_cast<uint32_t*>(&v);
}
__device__ __forceinline__ __half2 u2h(uint32_t v) {
    return *reinterpret_cast<__half2*>(&v);
}
__device__ __forceinline__ float ex2(float x) {
    float r;
    asm("ex2.approx.f32 %0, %1;" : "=f"(r) : "f"(x));
    return r;
}

// ---------------------------------------------------------------------------
// Conversion kernels
// ---------------------------------------------------------------------------
__global__ void cvt_f16_kernel(const float* __restrict__ in,
                               __half* __restrict__ out, int n)
{
    int i = (blockIdx.x * blockDim.x + threadIdx.x) * 8;
    if (i >= n) return;
    float4 a = *(const float4*)(in + i);
    float4 b = *(const float4*)(in + i + 4);
    __half h[8];
    h[0] = __float2half_rn(a.x); h[1] = __float2half_rn(a.y);
    h[2] = __float2half_rn(a.z); h[3] = __float2half_rn(a.w);
    h[4] = __float2half_rn(b.x); h[5] = __float2half_rn(b.y);
    h[6] = __float2half_rn(b.z); h[7] = __float2half_rn(b.w);
    *(uint4*)(out + i) = *(uint4*)h;
}

// W [K][N] row-major -> Wt fp16 [N][K]
__global__ void transpose_f16(const float* __restrict__ W,
                              __half* __restrict__ Tf, int K, int N)
{
    __shared__ float tile[32][33];
    int k0 = blockIdx.y * 32, n0 = blockIdx.x * 32;
    int tx = threadIdx.x, ty = threadIdx.y;
#pragma unroll
    for (int i = ty; i < 32; i += 8)
        tile[i][tx] = W[(size_t)(k0 + i) * N + n0 + tx];
    __syncthreads();
#pragma unroll
    for (int i = ty; i < 32; i += 8)
        Tf[(size_t)(n0 + i) * K + k0 + tx] = __float2half_rn(tile[tx][i]);
}

// ---------------------------------------------------------------------------
// mma.sync fp16 single-pass GEMM: C = A @ W^T + bias.
// BK=64, THREE-stage cp.async pipeline (loads get 2 compute-chunks of slack).
// Accumulation order identical to round 16 -> GEMM output bit-identical.
// ---------------------------------------------------------------------------
#define PAD 72
#define MAT_B (128 * PAD * 2)           // 18432
#define STAGE_B (2 * MAT_B)             // 36864 (A, B)
#define GEMM_SMEM (3 * STAGE_B)         // 110592
#define NCHUNK (GK / 64)                // 16

__global__ __launch_bounds__(256) void tc_gemm_mma(
    const __half* __restrict__ Af, const __half* __restrict__ Bf,
    const float* __restrict__ bias, float* __restrict__ Co,
    __half* __restrict__ Cf16, int N, int split_out)
{
    extern __shared__ char smem[];
    const uint32_t sb = smem_u32(smem);
    const int tid = threadIdx.x;
    const int wid = tid >> 5, lane = tid & 31;
    const int warp_m = wid >> 1, warp_n = wid & 1;
    const int m0 = blockIdx.y * 128, n0 = blockIdx.x * 128;

    const __half* srcs[2] = { Af + (size_t)m0 * GK, Bf + (size_t)n0 * GK };

    auto prefetch = [&](int c, int stage) {
        const int k0 = c * 64;
        const uint32_t so = sb + stage * STAGE_B;
#pragma unroll
        for (int msel = 0; msel < 2; msel++) {
#pragma unroll
            for (int i = 0; i < 4; i++) {
                int idx = tid + i * 256;
                int r = idx >> 3, seg = idx & 7;
                uint32_t dst = so + msel * MAT_B + (uint32_t)(r * PAD + seg * 8) * 2;
                cp_async16(dst, srcs[msel] + (size_t)r * GK + k0 + seg * 8);
            }
        }
    };

    float acc[2][8][4];
#pragma unroll
    for (int a = 0; a < 2; a++)
#pragma unroll
        for (int b = 0; b < 8; b++)
#pragma unroll
            for (int c = 0; c < 4; c++) acc[a][b][c] = 0.f;

    prefetch(0, 0); cp_commit();
    prefetch(1, 1); cp_commit();

    const int a_row = (lane & 15);
    const int a_col8 = (lane >> 4) << 3;
    const int b_tile = lane >> 3;
    const int b_rin = lane & 7;
    const int b_nrow = ((b_tile >> 1) << 3) + b_rin;
    const int b_kcol = (b_tile & 1) << 3;

    int st = 0;
    for (int c = 0; c < NCHUNK; c++) {
        // stage (c+2)%3 last held chunk c-1; trailing barrier of iter c-1
        // guarantees all warps finished reading it.
        if (c + 2 < NCHUNK) {
            int st2 = st + 2; if (st2 >= 3) st2 -= 3;
            prefetch(c + 2, st2); cp_commit();
        }
        if (c + 2 < NCHUNK)      cp_wait<2>();
        else if (c + 1 < NCHUNK) cp_wait<1>();
        else                     cp_wait<0>();
        __syncthreads();

        const uint32_t so = sb + st * STAGE_B;
#pragma unroll
        for (int ks = 0; ks < 4; ks++) {
            uint32_t aF[2][4];
#pragma unroll
            for (int mi = 0; mi < 2; mi++) {
                uint32_t off = (uint32_t)((warp_m * 32 + mi * 16 + a_row) * PAD
                                          + ks * 16 + a_col8) * 2;
                ldm_x4(aF[mi], so + off);
            }
#pragma unroll
            for (int nj = 0; nj < 4; nj++) {
                uint32_t bF[4];
                uint32_t off = (uint32_t)((warp_n * 64 + nj * 16 + b_nrow) * PAD
                                          + ks * 16 + b_kcol) * 2;
                ldm_x4(bF, so + MAT_B + off);
#pragma unroll
                for (int mi = 0; mi < 2; mi++) {
                    mma_f16_v(acc[mi][nj * 2],     aF[mi], bF[0], bF[1]);
                    mma_f16_v(acc[mi][nj * 2 + 1], aF[mi], bF[2], bF[3]);
                }
            }
        }
        __syncthreads();
        if (++st == 3) st = 0;
    }

    const int r_base = m0 + warp_m * 32 + (lane >> 2);
    const int c_base = n0 + warp_n * 64 + (lane & 3) * 2;
    if (split_out) {
#pragma unroll
        for (int mi = 0; mi < 2; mi++) {
#pragma unroll
            for (int nj8 = 0; nj8 < 8; nj8++) {
                int col = c_base + nj8 * 8;
                float b0 = __ldg(bias + col), b1 = __ldg(bias + col + 1);
                int r0 = r_base + mi * 16;
                __half2 p0 = __float22half2_rn(
                    make_float2(acc[mi][nj8][0] + b0, acc[mi][nj8][1] + b1));
                __half2 p1 = __float22half2_rn(
                    make_float2(acc[mi][nj8][2] + b0, acc[mi][nj8][3] + b1));
                *(uint32_t*)(Cf16 + (size_t)r0 * N + col)       = h2u(p0);
                *(uint32_t*)(Cf16 + (size_t)(r0 + 8) * N + col) = h2u(p1);
            }
        }
    } else {
#pragma unroll
        for (int mi = 0; mi < 2; mi++) {
#pragma unroll
            for (int nj8 = 0; nj8 < 8; nj8++) {
                int col = c_base + nj8 * 8;
                float b0 = __ldg(bias + col), b1 = __ldg(bias + col + 1);
                int r0 = r_base + mi * 16;
                Co[(size_t)r0 * N + col]           = acc[mi][nj8][0] + b0;
                Co[(size_t)r0 * N + col + 1]       = acc[mi][nj8][1] + b1;
                Co[(size_t)(r0 + 8) * N + col]     = acc[mi][nj8][2] + b0;
                Co[(size_t)(r0 + 8) * N + col + 1] = acc[mi][nj8][3] + b1;
            }
        }
    }
}

// ---------------------------------------------------------------------------
// Tensor-core causal flash attention — single-pass fp16, log2-domain softmax:
// Q fragments pre-scaled once by 0.125*log2(e); all exponentials are raw
// ex2.approx (base change is exact for softmax; saves ~66 FMA ops/tile).
// ---------------------------------------------------------------------------
#define PADA 72
#define KTB  9216
#define QB   18432
#define KVS  (2 * KTB)
#define KVBASE QB
#define FLASH_SMEM (QB + 2 * KVS)       // 55296

__global__ __launch_bounds__(256) void flash_mma_kernel(
    const __half* __restrict__ qkvf, __half* __restrict__ yf)
{
    extern __shared__ __align__(16) char smem[];
    const uint32_t sb = smem_u32(smem);
    const int tid = threadIdx.x;
    const int wid = tid >> 5, lane = tid & 31;
    const int bh = blockIdx.x, b = bh >> 4, h = bh & 15;
    const int qt = (T_ / 128 - 1) - blockIdx.y;  // long CTAs first
    const int q0 = qt * 128;
    const size_t rowbase = (size_t)b * T_ * C3;

    auto fillKV = [&](int kt, int s) {
        const int k0 = kt * 64;
        const uint32_t so = sb + KVBASE + s * KVS;
#pragma unroll
        for (int i = 0; i < 4; i++) {
            int idx = tid + i * 256;
            int mat = idx >> 9;            // 0=K 1=V
            int rem = idx & 511;
            int r = rem >> 3, seg = rem & 7;
            const __half* src = qkvf + rowbase + (size_t)(k0 + r) * C3
                                + (mat ? 2 * C_ : C_) + h * D_ + seg * 8;
            cp_async16(so + (uint32_t)(mat * KTB + r * 144 + seg * 16), src);
        }
    };

    // ---- stage Q ----
    {
#pragma unroll
        for (int i = 0; i < 4; i++) {
            int idx = tid + i * 256;
            int r = idx >> 3, seg = idx & 7;
            const __half* src = qkvf + rowbase + (size_t)(q0 + r) * C3
                                + h * D_ + seg * 8;
            cp_async16(sb + (uint32_t)(r * 144 + seg * 16), src);
        }
    }
    cp_commit();
    fillKV(0, 0);
    cp_commit();

    const int a_row = lane & 15;
    const int a_col8 = (lane >> 4) << 3;
    const int b_tile = lane >> 3;
    const int b_nrow = ((b_tile >> 1) << 3) + (lane & 7);
    const int b_kcol = (b_tile & 1) << 3;
    const int v_krow = ((b_tile & 1) << 3) + (lane & 7);
    const int v_ncol = (b_tile >> 1) << 3;

    cp_wait<1>();
    __syncthreads();

    // Q fragments, pre-scaled by 0.125*log2(e) so scores are in log2 domain.
    uint32_t aQ[4][4];
    {
        const __half2 qs = __float2half2_rn(0.18033688f);  // 0.125 * 1.4426950
#pragma unroll
        for (int ks = 0; ks < 4; ks++) {
            uint32_t off = (uint32_t)((wid * 16 + a_row) * PADA + ks * 16 + a_col8) * 2;
            ldm_x4(aQ[ks], sb + off);
#pragma unroll
            for (int i = 0; i < 4; i++)
                aQ[ks][i] = h2u(__hmul2(u2h(aQ[ks][i]), qs));
        }
    }

    float oacc[8][4];
#pragma unroll
    for (int i = 0; i < 8; i++)
#pragma unroll
        for (int j = 0; j < 4; j++) oacc[i][j] = 0.f;
    float mrow[2] = {-1e30f, -1e30f};
    float lrow[2] = {0.f, 0.f};

    const int ntiles = 2 * (qt + 1);
    for (int kt = 0; kt < ntiles; kt++) {
        const int s = kt & 1;
        const int k0 = kt * 64;
        __syncthreads();
        if (kt + 1 < ntiles) { fillKV(kt + 1, s ^ 1); cp_commit(); }
        if (kt + 1 < ntiles) cp_wait<1>(); else cp_wait<0>();
        __syncthreads();

        const uint32_t kvso = sb + KVBASE + s * KVS;

        // ---- S = Q @ K^T (already scaled; log2 domain) ----
        float sacc[8][4];
#pragma unroll
        for (int i = 0; i < 8; i++)
#pragma unroll
            for (int j = 0; j < 4; j++) sacc[i][j] = 0.f;
#pragma unroll
        for (int ks = 0; ks < 4; ks++) {
            uint32_t bK[4];
#pragma unroll
            for (int nj = 0; nj < 4; nj++) {
                uint32_t off = (uint32_t)((nj * 16 + b_nrow) * PADA
                                          + ks * 16 + b_kcol) * 2;
                ldm_x4(bK, kvso + off);
                mma_f16(sacc[nj * 2],     aQ[ks], bK[0], bK[1]);
                mma_f16(sacc[nj * 2 + 1], aQ[ks], bK[2], bK[3]);
            }
        }

        // ---- causal mask (last two tiles only) ----
        if (k0 >= q0) {
            const int qg = q0 + wid * 16 + (lane >> 2);
            const int cg = k0 + (lane & 3) * 2;
#pragma unroll
            for (int nb = 0; nb < 8; nb++) {
                int col = cg + nb * 8;
                if (col > qg)          sacc[nb][0] = -1e30f;
                if (col + 1 > qg)      sacc[nb][1] = -1e30f;
                if (col > qg + 8)      sacc[nb][2] = -1e30f;
                if (col + 1 > qg + 8)  sacc[nb][3] = -1e30f;
            }
        }

        // ---- online softmax (base 2) ----
        float mn0 = mrow[0], mn1 = mrow[1];
#pragma unroll
        for (int nb = 0; nb < 8; nb++) {
            mn0 = fmaxf(mn0, fmaxf(sacc[nb][0], sacc[nb][1]));
            mn1 = fmaxf(mn1, fmaxf(sacc[nb][2], sacc[nb][3]));
        }
        mn0 = fmaxf(mn0, __shfl_xor_sync(0xFFFFFFFF, mn0, 1));
        mn0 = fmaxf(mn0, __shfl_xor_sync(0xFFFFFFFF, mn0, 2));
        mn1 = fmaxf(mn1, __shfl_xor_sync(0xFFFFFFFF, mn1, 1));
        mn1 = fmaxf(mn1, __shfl_xor_sync(0xFFFFFFFF, mn1, 2));
        const float corr0 = ex2(mrow[0] - mn0);
        const float corr1 = ex2(mrow[1] - mn1);
        mrow[0] = mn0; mrow[1] = mn1;

        float ps0 = 0.f, ps1 = 0.f;
#pragma unroll
        for (int nb = 0; nb < 8; nb++) {
            sacc[nb][0] = ex2(sacc[nb][0] - mn0);
            sacc[nb][1] = ex2(sacc[nb][1] - mn0);
            sacc[nb][2] = ex2(sacc[nb][2] - mn1);
            sacc[nb][3] = ex2(sacc[nb][3] - mn1);
            ps0 += sacc[nb][0] + sacc[nb][1];
            ps1 += sacc[nb][2] + sacc[nb][3];
        }
        ps0 += __shfl_xor_sync(0xFFFFFFFF, ps0, 1);
        ps0 += __shfl_xor_sync(0xFFFFFFFF, ps0, 2);
        ps1 += __shfl_xor_sync(0xFFFFFFFF, ps1, 1);
        ps1 += __shfl_xor_sync(0xFFFFFFFF, ps1, 2);
        lrow[0] = lrow[0] * corr0 + ps0;
        lrow[1] = lrow[1] * corr1 + ps1;
#pragma unroll
        for (int nb = 0; nb < 8; nb++) {
            oacc[nb][0] *= corr0; oacc[nb][1] *= corr0;
            oacc[nb][2] *= corr1; oacc[nb][3] *= corr1;
        }

        // ---- O += P @ V ----
#pragma unroll
        for (int ks = 0; ks < 4; ks++) {
            uint32_t pF[4];
            pF[0] = h2u(__float22half2_rn(
                make_float2(sacc[2 * ks][0], sacc[2 * ks][1])));
            pF[1] = h2u(__float22half2_rn(
                make_float2(sacc[2 * ks][2], sacc[2 * ks][3])));
            pF[2] = h2u(__float22half2_rn(
                make_float2(sacc[2 * ks + 1][0], sacc[2 * ks + 1][1])));
            pF[3] = h2u(__float22half2_rn(
                make_float2(sacc[2 * ks + 1][2], sacc[2 * ks + 1][3])));
#pragma unroll
            for (int nj = 0; nj < 4; nj++) {
                uint32_t bV[4];
                uint32_t off = (uint32_t)((ks * 16 + v_krow) * PADA
                                          + nj * 16 + v_ncol) * 2;
                ldm_x4_trans(bV, kvso + KTB + off);
                mma_f16(oacc[nj * 2],     pF, bV[0], bV[1]);
                mma_f16(oacc[nj * 2 + 1], pF, bV[2], bV[3]);
            }
        }
    }

    // ---- normalize and write y as single fp16 ----
    const float inv0 = 1.f / lrow[0];
    const float inv1 = 1.f / lrow[1];
    const int rg = q0 + wid * 16 + (lane >> 2);
    const size_t e0 = ((size_t)b * T_ + rg) * C_ + h * D_ + (lane & 3) * 2;
#pragma unroll
    for (int nb = 0; nb < 8; nb++) {
        __half2 o0 = __float22half2_rn(
            make_float2(oacc[nb][0] * inv0, oacc[nb][1] * inv0));
        __half2 o1 = __float22half2_rn(
            make_float2(oacc[nb][2] * inv1, oacc[nb][3] * inv1));
        *(uint32_t*)(yf + e0 + nb * 8)          = h2u(o0);
        *(uint32_t*)(yf + e0 + 8 * C_ + nb * 8) = h2u(o1);
    }
}

// ---------------------------------------------------------------------------
extern "C" void kernel_launch(void* const* d_in, const int* in_sizes, int n_in,
                              void* d_out, int out_size)
{
    const float* x      = (const float*)d_in[0];
    const float* W_attn = (const float*)d_in[1];
    const float* b_attn = (const float*)d_in[2];
    const float* W_proj = (const float*)d_in[3];
    const float* b_proj = (const float*)d_in[4];
    float* out = (float*)d_out;

    __half *qkvf, *xf, *yf, *waf, *wpf;
    cudaGetSymbolAddress((void**)&qkvf, g_qkvf);
    cudaGetSymbolAddress((void**)&xf, g_xf);
    cudaGetSymbolAddress((void**)&yf, g_yf);
    cudaGetSymbolAddress((void**)&waf, g_waf);
    cudaGetSymbolAddress((void**)&wpf, g_wpf);

    cudaFuncSetAttribute(tc_gemm_mma, cudaFuncAttributeMaxDynamicSharedMemorySize,
                         GEMM_SMEM);
    cudaFuncSetAttribute(flash_mma_kernel,
                         cudaFuncAttributeMaxDynamicSharedMemorySize, FLASH_SMEM);

    const int NTOK_EL = M_TOK * C_;

    // 1) x -> fp16
    cvt_f16_kernel<<<NTOK_EL / 8 / 256, 256>>>(x, xf, NTOK_EL);
    // 2) transpose weights -> fp16
    transpose_f16<<<dim3(C3 / 32, C_ / 32), dim3(32, 8)>>>(W_attn, waf, C_, C3);
    transpose_f16<<<dim3(C_ / 32, C_ / 32), dim3(32, 8)>>>(W_proj, wpf, C_, C_);
    // 3) QKV GEMM (single-pass fp16, BK=64, 3-stage) -> qkv fp16
    tc_gemm_mma<<<dim3(C3 / 128, M_TOK / 128), 256, GEMM_SMEM>>>(
        xf, waf, b_attn, nullptr, qkvf, C3, 1);
    // 4) causal flash attention (single-pass fp16, log2 softmax)
    flash_mma_kernel<<<dim3(B_ * H_, T_ / 128), 256, FLASH_SMEM>>>(qkvf, yf);
    // 5) proj GEMM (single-pass fp16, BK=64, 3-stage) -> d_out fp32
    tc_gemm_mma<<<dim3(C_ / 128, M_TOK / 128), 256, GEMM_SMEM>>>(
        yf, wpf, b_proj, out, nullptr, C_, 0);
}